// round 1
// baseline (speedup 1.0000x reference)
#include <cuda_runtime.h>
#include <math.h>

#define BB 2
#define TT 2048
#define DD 2048
#define HH 32
#define GG 8
#define HDIM 64
#define GROUPSZ 4
#define KVD (GG*HDIM)   // 512

// Scratch (no allocations allowed -> __device__ globals)
__device__ float g_q[(size_t)BB*TT*HH*HDIM];     // [B*T][H][HD]
__device__ float g_k[(size_t)BB*TT*GG*HDIM];     // [B*T][G][HD]
__device__ float g_v[(size_t)BB*TT*GG*HDIM];     // [B*T][G][HD]
__device__ float g_ctxT[(size_t)BB*DD*TT];       // [B][D][T]  (transposed ctx)

// ---------------------------------------------------------------------------
// Generic tiled SGEMM: C[m][n] = sum_k A[m][k] * W[k][n]
// BM=64, BN=64, BK=16, 256 threads, 4x4 per thread.
// blockIdx.z = batch (A and C get batch strides; W shared).
// ---------------------------------------------------------------------------
__global__ __launch_bounds__(256) void gemm64_kernel(
    const float* __restrict__ A, const float* __restrict__ W,
    float* __restrict__ C, int M, int N, int K,
    long aBatchStride, long cBatchStride)
{
    A += (long)blockIdx.z * aBatchStride;
    C += (long)blockIdx.z * cBatchStride;

    __shared__ float As[16][68];   // [k][m], padded (68 floats = 272B, 16B-aligned rows)
    __shared__ float Bs[16][64];   // [k][n]

    const int tid = threadIdx.x;
    const int tx = tid & 15;
    const int ty = tid >> 4;
    const int row0 = blockIdx.y * 64;
    const int col0 = blockIdx.x * 64;

    float acc[4][4];
#pragma unroll
    for (int i = 0; i < 4; i++)
#pragma unroll
        for (int j = 0; j < 4; j++) acc[i][j] = 0.f;

    const int am = tid >> 2;          // 0..63
    const int ak = (tid & 3) * 4;     // 0,4,8,12
    const int bk = tid >> 4;          // 0..15
    const int bn = (tid & 15) * 4;    // 0..60

    for (int k0 = 0; k0 < K; k0 += 16) {
        float4 a4 = *(const float4*)&A[(long)(row0 + am) * K + k0 + ak];
        As[ak + 0][am] = a4.x;
        As[ak + 1][am] = a4.y;
        As[ak + 2][am] = a4.z;
        As[ak + 3][am] = a4.w;
        *(float4*)&Bs[bk][bn] = *(const float4*)&W[(long)(k0 + bk) * N + col0 + bn];
        __syncthreads();

#pragma unroll
        for (int kk = 0; kk < 16; kk++) {
            float4 av = *(const float4*)&As[kk][ty * 4];
            float4 bv = *(const float4*)&Bs[kk][tx * 4];
            float ar[4] = {av.x, av.y, av.z, av.w};
            float br[4] = {bv.x, bv.y, bv.z, bv.w};
#pragma unroll
            for (int i = 0; i < 4; i++)
#pragma unroll
                for (int j = 0; j < 4; j++)
                    acc[i][j] += ar[i] * br[j];
        }
        __syncthreads();
    }

#pragma unroll
    for (int i = 0; i < 4; i++) {
        float4 r = make_float4(acc[i][0], acc[i][1], acc[i][2], acc[i][3]);
        *(float4*)&C[(long)(row0 + ty * 4 + i) * N + col0 + tx * 4] = r;
    }
}

// ---------------------------------------------------------------------------
// RoPE (in place). buf layout: [B*T][nHeads][HD]. Pairs (d, d+32).
// ---------------------------------------------------------------------------
__global__ void rope_kernel(float* __restrict__ buf, int nHeads, long totalPairs)
{
    long idx = (long)blockIdx.x * blockDim.x + threadIdx.x;
    if (idx >= totalPairs) return;
    int d = (int)(idx & 31);                 // 0..31
    long rest = idx >> 5;
    int h = (int)(rest % nHeads);
    long bt = rest / nHeads;
    int t = (int)(bt % TT);

    float e = (float)d * (2.0f / (float)HDIM);
    float inv = 1.0f / powf(10000.0f, e);
    float ang = (float)t * inv;
    float s, c;
    sincosf(ang, &s, &c);

    long base = (bt * nHeads + h) * HDIM + d;
    float x1 = buf[base];
    float x2 = buf[base + 32];
    buf[base]      = x1 * c - x2 * s;
    buf[base + 32] = x2 * c + x1 * s;
}

// ---------------------------------------------------------------------------
// Flash-style causal attention. One thread per query row, 128 q rows / block.
// Q row + O accumulator in registers; K/V 64x64 tiles in smem (broadcast reads);
// score tile staged in smem so rescale happens once per K tile.
// Writes ctxT[b][h*HD+d][t]  (transposed for the final GEMM).
// Dynamic smem: Ks(16KB) + Vs(16KB) + Ss(32KB) = 64KB.
// ---------------------------------------------------------------------------
#define QTILE 128
#define KTILE 64

__global__ __launch_bounds__(QTILE) void attn_kernel(
    const float* __restrict__ q, const float* __restrict__ k,
    const float* __restrict__ v, float* __restrict__ ctxT)
{
    extern __shared__ float smem[];
    float* Ks = smem;                       // [KTILE][HD]
    float* Vs = smem + KTILE * HDIM;        // [KTILE][HD]
    float* Ss = smem + 2 * KTILE * HDIM;    // [KTILE][QTILE]

    const int qt = blockIdx.x;
    const int h  = blockIdx.y;
    const int b  = blockIdx.z;
    const int g  = h / GROUPSZ;
    const int tid = threadIdx.x;
    const int qi = qt * QTILE + tid;

    const float scale = 0.125f;   // 1/sqrt(64)

    float qreg[HDIM];
    {
        const float* qptr = q + (((long)(b * TT + qi) * HH + h) * HDIM);
#pragma unroll
        for (int d4 = 0; d4 < HDIM / 4; d4++) {
            float4 t4 = *(const float4*)(qptr + d4 * 4);
            qreg[d4 * 4 + 0] = t4.x * scale;
            qreg[d4 * 4 + 1] = t4.y * scale;
            qreg[d4 * 4 + 2] = t4.z * scale;
            qreg[d4 * 4 + 3] = t4.w * scale;
        }
    }

    float O[HDIM];
#pragma unroll
    for (int d = 0; d < HDIM; d++) O[d] = 0.f;
    float m = -INFINITY, l = 0.f;

    const int nkt = 2 * qt + 2;   // tiles covering [0, qt*128+128)

    for (int kt = 0; kt < nkt; kt++) {
        // cooperative load of K and V tiles (64 rows x 64 dims, float4 granularity)
        const long kvbase = ((long)(b * TT + kt * KTILE) * GG + g) * HDIM;
#pragma unroll
        for (int r = 0; r < 8; r++) {
            int e  = r * QTILE + tid;     // 0..1023 float4 slots
            int j  = e >> 4;              // row 0..63
            int d4 = e & 15;              // float4 col
            *(float4*)&Ks[j * HDIM + d4 * 4] =
                *(const float4*)&k[kvbase + (long)j * KVD + d4 * 4];
            *(float4*)&Vs[j * HDIM + d4 * 4] =
                *(const float4*)&v[kvbase + (long)j * KVD + d4 * 4];
        }
        __syncthreads();

        // pass 1: scores for this tile, track new max
        float mt = m;
        for (int j = 0; j < KTILE; j++) {
            float s = 0.f;
#pragma unroll
            for (int d4 = 0; d4 < HDIM / 4; d4++) {
                float4 k4 = *(const float4*)&Ks[j * HDIM + d4 * 4];
                s += qreg[d4 * 4 + 0] * k4.x;
                s += qreg[d4 * 4 + 1] * k4.y;
                s += qreg[d4 * 4 + 2] * k4.z;
                s += qreg[d4 * 4 + 3] * k4.w;
            }
            int kj = kt * KTILE + j;
            s = (kj <= qi) ? s : -INFINITY;
            mt = fmaxf(mt, s);
            Ss[j * QTILE + tid] = s;
        }

        // rescale previous state once per tile
        float corr = __expf(m - mt);     // m=-inf first tile -> 0
        float lnew = l * corr;
#pragma unroll
        for (int d = 0; d < HDIM; d++) O[d] *= corr;
        m = mt;

        // pass 2: p = exp(s - m), accumulate PV
        for (int j = 0; j < KTILE; j++) {
            float p = __expf(Ss[j * QTILE + tid] - mt);
            lnew += p;
#pragma unroll
            for (int d4 = 0; d4 < HDIM / 4; d4++) {
                float4 v4 = *(const float4*)&Vs[j * HDIM + d4 * 4];
                O[d4 * 4 + 0] += p * v4.x;
                O[d4 * 4 + 1] += p * v4.y;
                O[d4 * 4 + 2] += p * v4.z;
                O[d4 * 4 + 3] += p * v4.w;
            }
        }
        l = lnew;
        __syncthreads();
    }

    const float inv_l = 1.0f / l;
    const long obase = ((long)b * DD + (long)h * HDIM) * TT + qi;
#pragma unroll
    for (int d = 0; d < HDIM; d++)
        ctxT[obase + (long)d * TT] = O[d] * inv_l;   // coalesced across tid
}

// ---------------------------------------------------------------------------
// Launch
// ---------------------------------------------------------------------------
extern "C" void kernel_launch(void* const* d_in, const int* in_sizes, int n_in,
                              void* d_out, int out_size)
{
    const float* x  = (const float*)d_in[0];
    const float* Wq = (const float*)d_in[1];
    const float* Wk = (const float*)d_in[2];
    const float* Wv = (const float*)d_in[3];
    const float* Wo = (const float*)d_in[4];
    float* out = (float*)d_out;

    float *qb, *kb, *vb, *ctxT;
    cudaGetSymbolAddress((void**)&qb,   g_q);
    cudaGetSymbolAddress((void**)&kb,   g_k);
    cudaGetSymbolAddress((void**)&vb,   g_v);
    cudaGetSymbolAddress((void**)&ctxT, g_ctxT);

    const int M = BB * TT;   // 4096

    // Projections
    gemm64_kernel<<<dim3(DD / 64,  M / 64, 1), 256>>>(x, Wq, qb, M, DD,  DD, 0, 0);
    gemm64_kernel<<<dim3(KVD / 64, M / 64, 1), 256>>>(x, Wk, kb, M, KVD, DD, 0, 0);
    gemm64_kernel<<<dim3(KVD / 64, M / 64, 1), 256>>>(x, Wv, vb, M, KVD, DD, 0, 0);

    // RoPE
    {
        long qPairs = (long)BB * TT * HH * (HDIM / 2);   // 4,194,304
        long kPairs = (long)BB * TT * GG * (HDIM / 2);   // 1,048,576
        rope_kernel<<<(int)((qPairs + 255) / 256), 256>>>(qb, HH, qPairs);
        rope_kernel<<<(int)((kPairs + 255) / 256), 256>>>(kb, GG, kPairs);
    }

    // Attention
    {
        int smemBytes = (2 * KTILE * HDIM + KTILE * QTILE) * (int)sizeof(float); // 64KB
        cudaFuncSetAttribute(attn_kernel, cudaFuncAttributeMaxDynamicSharedMemorySize,
                             smemBytes);
        attn_kernel<<<dim3(TT / QTILE, HH, BB), QTILE, smemBytes>>>(qb, kb, vb, ctxT);
    }

    // Final projection: out[b] = ctxT[b] (2048x2048) @ Wo (2048x2048)
    gemm64_kernel<<<dim3(DD / 64, DD / 64, BB), 256>>>(
        ctxT, Wo, out, DD, DD, DD, (long)DD * TT, (long)TT * DD);
}

// round 4
// speedup vs baseline: 1.7060x; 1.7060x over previous
#include <cuda_runtime.h>
#include <cuda_bf16.h>
#include <math.h>
#include <stdint.h>

#define BB 2
#define TT 2048
#define DD 2048
#define HH 32
#define GG 8
#define HDIM 64
#define GROUPSZ 4
#define KVD (GG*HDIM)   // 512

// ---------------------------------------------------------------------------
// Scratch (__device__ globals; no allocations allowed)
// ---------------------------------------------------------------------------
__device__ float g_q[(size_t)BB*TT*HH*HDIM];     // [B*T][H][HD]
__device__ float g_k[(size_t)BB*TT*GG*HDIM];     // [B*T][G][HD]
__device__ float g_v[(size_t)BB*TT*GG*HDIM];     // [B*T][G][HD]
__device__ float g_ctxT[(size_t)BB*DD*TT];       // [B][D][T]

// bf16 hi/lo split buffers
__device__ __nv_bfloat16 g_xhi[(size_t)BB*TT*DD];
__device__ __nv_bfloat16 g_xlo[(size_t)BB*TT*DD];
__device__ __nv_bfloat16 g_chi[(size_t)BB*DD*TT];
__device__ __nv_bfloat16 g_clo[(size_t)BB*DD*TT];
// transposed weights [N][K]
__device__ __nv_bfloat16 g_wqthi[(size_t)DD*DD];
__device__ __nv_bfloat16 g_wqtlo[(size_t)DD*DD];
__device__ __nv_bfloat16 g_wkthi[(size_t)KVD*DD];
__device__ __nv_bfloat16 g_wktlo[(size_t)KVD*DD];
__device__ __nv_bfloat16 g_wvthi[(size_t)KVD*DD];
__device__ __nv_bfloat16 g_wvtlo[(size_t)KVD*DD];
__device__ __nv_bfloat16 g_wothi[(size_t)DD*DD];
__device__ __nv_bfloat16 g_wotlo[(size_t)DD*DD];

// ---------------------------------------------------------------------------
// PTX helpers (sm_80-era: cp.async + ldmatrix + mma.sync — valid on sm_103)
// ---------------------------------------------------------------------------
__device__ __forceinline__ uint32_t smem_to_u32(const void* p) {
    uint32_t a;
    asm("{ .reg .u64 tmp; cvta.to.shared.u64 tmp, %1; cvt.u32.u64 %0, tmp; }"
        : "=r"(a) : "l"(p));
    return a;
}
__device__ __forceinline__ void cp_async16(uint32_t dst, const void* src) {
    asm volatile("cp.async.cg.shared.global [%0], [%1], 16;" :: "r"(dst), "l"(src));
}
__device__ __forceinline__ void cp_commit() {
    asm volatile("cp.async.commit_group;" ::: "memory");
}
template <int N> __device__ __forceinline__ void cp_wait() {
    asm volatile("cp.async.wait_group %0;" :: "n"(N) : "memory");
}
__device__ __forceinline__ void ldsm_x4(uint32_t r[4], uint32_t addr) {
    asm volatile("ldmatrix.sync.aligned.m8n8.x4.shared.b16 {%0,%1,%2,%3}, [%4];"
                 : "=r"(r[0]), "=r"(r[1]), "=r"(r[2]), "=r"(r[3]) : "r"(addr));
}
__device__ __forceinline__ void mma_bf16(float c[4], const uint32_t a[4],
                                         const uint32_t b0, const uint32_t b1) {
    asm volatile(
        "mma.sync.aligned.m16n8k16.row.col.f32.bf16.bf16.f32 "
        "{%0,%1,%2,%3}, {%4,%5,%6,%7}, {%8,%9}, {%0,%1,%2,%3};"
        : "+f"(c[0]), "+f"(c[1]), "+f"(c[2]), "+f"(c[3])
        : "r"(a[0]), "r"(a[1]), "r"(a[2]), "r"(a[3]), "r"(b0), "r"(b1));
}

// ---------------------------------------------------------------------------
// bf16 hi/lo split of a float array
// ---------------------------------------------------------------------------
__global__ void split_kernel(const float* __restrict__ in,
                             __nv_bfloat16* __restrict__ hi,
                             __nv_bfloat16* __restrict__ lo, long n4)
{
    long i = (long)blockIdx.x * blockDim.x + threadIdx.x;
    if (i >= n4) return;
    float4 v = ((const float4*)in)[i];
    __nv_bfloat16 h0 = __float2bfloat16(v.x);
    __nv_bfloat16 h1 = __float2bfloat16(v.y);
    __nv_bfloat16 h2 = __float2bfloat16(v.z);
    __nv_bfloat16 h3 = __float2bfloat16(v.w);
    __nv_bfloat162 hA = __nv_bfloat162(h0, h1);
    __nv_bfloat162 hB = __nv_bfloat162(h2, h3);
    __nv_bfloat162 lA = __nv_bfloat162(__float2bfloat16(v.x - __bfloat162float(h0)),
                                       __float2bfloat16(v.y - __bfloat162float(h1)));
    __nv_bfloat162 lB = __nv_bfloat162(__float2bfloat16(v.z - __bfloat162float(h2)),
                                       __float2bfloat16(v.w - __bfloat162float(h3)));
    ((__nv_bfloat162*)hi)[i * 2 + 0] = hA;
    ((__nv_bfloat162*)hi)[i * 2 + 1] = hB;
    ((__nv_bfloat162*)lo)[i * 2 + 0] = lA;
    ((__nv_bfloat162*)lo)[i * 2 + 1] = lB;
}

// ---------------------------------------------------------------------------
// Transpose + split: W [K,N] fp32 -> Wt hi/lo [N,K] bf16
// ---------------------------------------------------------------------------
__global__ __launch_bounds__(1024) void transpose_split_kernel(
    const float* __restrict__ W,
    __nv_bfloat16* __restrict__ Thi, __nv_bfloat16* __restrict__ Tlo,
    int K, int N)
{
    __shared__ float tile[32][33];
    int tx = threadIdx.x, ty = threadIdx.y;
    int n0 = blockIdx.x * 32, k0 = blockIdx.y * 32;
    tile[ty][tx] = W[(long)(k0 + ty) * N + n0 + tx];
    __syncthreads();
    float v = tile[tx][ty];
    __nv_bfloat16 h = __float2bfloat16(v);
    __nv_bfloat16 l = __float2bfloat16(v - __bfloat162float(h));
    long oidx = (long)(n0 + ty) * K + k0 + tx;
    Thi[oidx] = h;
    Tlo[oidx] = l;
}

// ---------------------------------------------------------------------------
// HMMA GEMM: C[m][n] = sum_k A[m][k]*B[n][k]  (B pre-transposed, [N][K])
// bf16 hi/lo 3-term split: D += Ah*Bh + Al*Bh + Ah*Bl  (fp32 accumulate)
// CTA 128x128, KC=64, cp.async double buffer, 8 warps (2x4), 64x32 warp tiles.
// smem tiles: 128 rows x 64 bf16 (128B rows) with XOR-8 16B-chunk swizzle.
// ---------------------------------------------------------------------------
#define GM_TILE 128
#define KC      64
#define TILEB   (GM_TILE * KC * 2)      // 16384 bytes per tile
#define STAGEB  (4 * TILEB)             // Ah,Al,Bh,Bl = 64KB
#define GEMM_SMEM (2 * STAGEB)          // 128KB

__global__ __launch_bounds__(256, 1)
void hmma_gemm_kernel(const __nv_bfloat16* __restrict__ Ahi,
                      const __nv_bfloat16* __restrict__ Alo,
                      const __nv_bfloat16* __restrict__ Bhi,
                      const __nv_bfloat16* __restrict__ Blo,
                      float* __restrict__ C, int N, int K,
                      long aBatchStride, long cBatchStride)
{
    extern __shared__ __align__(128) char smem[];
    const uint32_t smem_base = smem_to_u32(smem);
    const int tid = threadIdx.x;
    const int wid = tid >> 5;
    const int lid = tid & 31;

    Ahi += (long)blockIdx.z * aBatchStride;
    Alo += (long)blockIdx.z * aBatchStride;
    C   += (long)blockIdx.z * cBatchStride;

    const int row0 = blockIdx.y * GM_TILE;
    const int col0 = blockIdx.x * GM_TILE;
    const int Rw = (wid >> 2) * 64;     // warp row offset in tile
    const int Cw = (wid & 3) * 32;      // warp col offset in tile

    // accumulators: 4 m-frags x 4 n-frags x 4 f32
    float acc[4][4][4];
#pragma unroll
    for (int i = 0; i < 4; i++)
#pragma unroll
        for (int j = 0; j < 4; j++)
#pragma unroll
            for (int r = 0; r < 4; r++) acc[i][j][r] = 0.f;

    // ldmatrix lane geometry
    const int aMat  = lid >> 3;
    const int aRow  = ((aMat & 1) << 3) + (lid & 7);     // row within frag
    const int aCAdd = aMat >> 1;                         // 16B k-seg select
    const int bRow  = ((lid >> 4) << 3) + (lid & 7);     // n-row within 16
    const int bCAdd = (lid >> 3) & 1;
    const int sw    = lid & 7;                           // swizzle key (row&7)

    const int nch = K / KC;

    // stage loader: 4 tiles x 1024 16B-chunks, 16 per thread
    auto load_stage = [&](int buf, int k0) {
        const __nv_bfloat16* srcs[4] = {Ahi, Alo, Bhi, Blo};
        uint32_t stage = smem_base + buf * STAGEB;
#pragma unroll
        for (int t = 0; t < 4; t++) {
            const __nv_bfloat16* base = srcs[t];
            const int r0 = (t < 2) ? row0 : col0;
            uint32_t tileBase = stage + t * TILEB;
#pragma unroll
            for (int i = 0; i < 4; i++) {
                int e = i * 256 + tid;
                int r = e >> 3;
                int c = e & 7;
                uint32_t dst = tileBase + r * 128 + ((c ^ (r & 7)) << 4);
                cp_async16(dst, base + (size_t)(r0 + r) * K + k0 + c * 8);
            }
        }
        cp_commit();
    };

    load_stage(0, 0);

    for (int ch = 0; ch < nch; ch++) {
        if (ch + 1 < nch) {
            load_stage((ch + 1) & 1, (ch + 1) * KC);
            cp_wait<1>();
        } else {
            cp_wait<0>();
        }
        __syncthreads();

        uint32_t stage = smem_base + (ch & 1) * STAGEB;
        uint32_t tAh = stage + 0 * TILEB;
        uint32_t tAl = stage + 1 * TILEB;
        uint32_t tBh = stage + 2 * TILEB;
        uint32_t tBl = stage + 3 * TILEB;

#pragma unroll
        for (int ks = 0; ks < KC / 16; ks++) {
            uint32_t ah[4][4], al[4][4], bh[4][2], bl[4][2];
            const int c16 = ks * 2;
#pragma unroll
            for (int mf = 0; mf < 4; mf++) {
                int r = Rw + mf * 16 + aRow;
                uint32_t off = r * 128 + (((c16 + aCAdd) ^ sw) << 4);
                ldsm_x4(ah[mf], tAh + off);
                ldsm_x4(al[mf], tAl + off);
            }
#pragma unroll
            for (int np = 0; np < 2; np++) {
                int r = Cw + np * 16 + bRow;
                uint32_t off = r * 128 + (((c16 + bCAdd) ^ sw) << 4);
                uint32_t t4[4];
                ldsm_x4(t4, tBh + off);
                bh[np * 2][0] = t4[0]; bh[np * 2][1] = t4[1];
                bh[np * 2 + 1][0] = t4[2]; bh[np * 2 + 1][1] = t4[3];
                ldsm_x4(t4, tBl + off);
                bl[np * 2][0] = t4[0]; bl[np * 2][1] = t4[1];
                bl[np * 2 + 1][0] = t4[2]; bl[np * 2 + 1][1] = t4[3];
            }
            // pass 1: Ah*Bh
#pragma unroll
            for (int mf = 0; mf < 4; mf++)
#pragma unroll
                for (int nf = 0; nf < 4; nf++)
                    mma_bf16(acc[mf][nf], ah[mf], bh[nf][0], bh[nf][1]);
            // pass 2: Al*Bh
#pragma unroll
            for (int mf = 0; mf < 4; mf++)
#pragma unroll
                for (int nf = 0; nf < 4; nf++)
                    mma_bf16(acc[mf][nf], al[mf], bh[nf][0], bh[nf][1]);
            // pass 3: Ah*Bl
#pragma unroll
            for (int mf = 0; mf < 4; mf++)
#pragma unroll
                for (int nf = 0; nf < 4; nf++)
                    mma_bf16(acc[mf][nf], ah[mf], bl[nf][0], bl[nf][1]);
        }
        __syncthreads();
    }

    // epilogue: stage through smem for coalesced float4 stores
    float* stage = (float*)smem;            // 128 x 132 f32 = 67.6KB (fits)
    const int g  = lid >> 2;
    const int tg = lid & 3;
#pragma unroll
    for (int mf = 0; mf < 4; mf++)
#pragma unroll
        for (int nf = 0; nf < 4; nf++) {
            int row = Rw + mf * 16 + g;
            int col = Cw + nf * 8 + 2 * tg;
            stage[row * 132 + col]           = acc[mf][nf][0];
            stage[row * 132 + col + 1]       = acc[mf][nf][1];
            stage[(row + 8) * 132 + col]     = acc[mf][nf][2];
            stage[(row + 8) * 132 + col + 1] = acc[mf][nf][3];
        }
    __syncthreads();
    // 128 rows x 32 float4 = 4096 float4 slots, 256 threads -> 16 iterations
#pragma unroll
    for (int i = 0; i < 16; i++) {
        int e = i * 256 + tid;          // 0..4095 float4 slots
        int r = e >> 5;                 // 0..127
        int c4 = e & 31;                // 0..31
        float4 v = *(float4*)&stage[r * 132 + c4 * 4];
        *(float4*)&C[(size_t)(row0 + r) * N + col0 + c4 * 4] = v;
    }
}

// ---------------------------------------------------------------------------
// RoPE (in place). buf layout: [B*T][nHeads][HD]. Pairs (d, d+32).
// ---------------------------------------------------------------------------
__global__ void rope_kernel(float* __restrict__ buf, int nHeads, long totalPairs)
{
    long idx = (long)blockIdx.x * blockDim.x + threadIdx.x;
    if (idx >= totalPairs) return;
    int d = (int)(idx & 31);
    long rest = idx >> 5;
    int h = (int)(rest % nHeads);
    long bt = rest / nHeads;
    int t = (int)(bt % TT);

    float e = (float)d * (2.0f / (float)HDIM);
    float inv = 1.0f / powf(10000.0f, e);
    float ang = (float)t * inv;
    float s, c;
    sincosf(ang, &s, &c);

    long base = (bt * nHeads + h) * HDIM + d;
    float x1 = buf[base];
    float x2 = buf[base + 32];
    buf[base]      = x1 * c - x2 * s;
    buf[base + 32] = x2 * c + x1 * s;
}

// ---------------------------------------------------------------------------
// Flash-style causal attention (fp32 SIMT). Writes ctxT[b][h*HD+d][t].
// ---------------------------------------------------------------------------
#define QTILE 128
#define KTILE 64

__global__ __launch_bounds__(QTILE) void attn_kernel(
    const float* __restrict__ q, const float* __restrict__ k,
    const float* __restrict__ v, float* __restrict__ ctxT)
{
    extern __shared__ float smemf[];
    float* Ks = smemf;
    float* Vs = smemf + KTILE * HDIM;
    float* Ss = smemf + 2 * KTILE * HDIM;

    const int qt = blockIdx.x;
    const int h  = blockIdx.y;
    const int b  = blockIdx.z;
    const int g  = h / GROUPSZ;
    const int tid = threadIdx.x;
    const int qi = qt * QTILE + tid;

    const float scale = 0.125f;

    float qreg[HDIM];
    {
        const float* qptr = q + (((long)(b * TT + qi) * HH + h) * HDIM);
#pragma unroll
        for (int d4 = 0; d4 < HDIM / 4; d4++) {
            float4 t4 = *(const float4*)(qptr + d4 * 4);
            qreg[d4 * 4 + 0] = t4.x * scale;
            qreg[d4 * 4 + 1] = t4.y * scale;
            qreg[d4 * 4 + 2] = t4.z * scale;
            qreg[d4 * 4 + 3] = t4.w * scale;
        }
    }

    float O[HDIM];
#pragma unroll
    for (int d = 0; d < HDIM; d++) O[d] = 0.f;
    float m = -INFINITY, l = 0.f;

    const int nkt = 2 * qt + 2;

    for (int kt = 0; kt < nkt; kt++) {
        const long kvbase = ((long)(b * TT + kt * KTILE) * GG + g) * HDIM;
#pragma unroll
        for (int r = 0; r < 8; r++) {
            int e  = r * QTILE + tid;
            int j  = e >> 4;
            int d4 = e & 15;
            *(float4*)&Ks[j * HDIM + d4 * 4] =
                *(const float4*)&k[kvbase + (long)j * KVD + d4 * 4];
            *(float4*)&Vs[j * HDIM + d4 * 4] =
                *(const float4*)&v[kvbase + (long)j * KVD + d4 * 4];
        }
        __syncthreads();

        float mt = m;
        for (int j = 0; j < KTILE; j++) {
            float s = 0.f;
#pragma unroll
            for (int d4 = 0; d4 < HDIM / 4; d4++) {
                float4 k4 = *(const float4*)&Ks[j * HDIM + d4 * 4];
                s += qreg[d4 * 4 + 0] * k4.x;
                s += qreg[d4 * 4 + 1] * k4.y;
                s += qreg[d4 * 4 + 2] * k4.z;
                s += qreg[d4 * 4 + 3] * k4.w;
            }
            int kj = kt * KTILE + j;
            s = (kj <= qi) ? s : -INFINITY;
            mt = fmaxf(mt, s);
            Ss[j * QTILE + tid] = s;
        }

        float corr = __expf(m - mt);
        float lnew = l * corr;
#pragma unroll
        for (int d = 0; d < HDIM; d++) O[d] *= corr;
        m = mt;

        for (int j = 0; j < KTILE; j++) {
            float p = __expf(Ss[j * QTILE + tid] - mt);
            lnew += p;
#pragma unroll
            for (int d4 = 0; d4 < HDIM / 4; d4++) {
                float4 v4 = *(const float4*)&Vs[j * HDIM + d4 * 4];
                O[d4 * 4 + 0] += p * v4.x;
                O[d4 * 4 + 1] += p * v4.y;
                O[d4 * 4 + 2] += p * v4.z;
                O[d4 * 4 + 3] += p * v4.w;
            }
        }
        l = lnew;
        __syncthreads();
    }

    const float inv_l = 1.0f / l;
    const long obase = ((long)b * DD + (long)h * HDIM) * TT + qi;
#pragma unroll
    for (int d = 0; d < HDIM; d++)
        ctxT[obase + (long)d * TT] = O[d] * inv_l;
}

// ---------------------------------------------------------------------------
// Launch
// ---------------------------------------------------------------------------
extern "C" void kernel_launch(void* const* d_in, const int* in_sizes, int n_in,
                              void* d_out, int out_size)
{
    const float* x  = (const float*)d_in[0];
    const float* Wq = (const float*)d_in[1];
    const float* Wk = (const float*)d_in[2];
    const float* Wv = (const float*)d_in[3];
    const float* Wo = (const float*)d_in[4];
    float* out = (float*)d_out;

    float *qb, *kb, *vb, *ctxT;
    cudaGetSymbolAddress((void**)&qb,   g_q);
    cudaGetSymbolAddress((void**)&kb,   g_k);
    cudaGetSymbolAddress((void**)&vb,   g_v);
    cudaGetSymbolAddress((void**)&ctxT, g_ctxT);
    __nv_bfloat16 *xhi, *xlo, *chi, *clo;
    __nv_bfloat16 *wqh, *wql, *wkh, *wkl, *wvh, *wvl, *woh, *wol;
    cudaGetSymbolAddress((void**)&xhi, g_xhi);
    cudaGetSymbolAddress((void**)&xlo, g_xlo);
    cudaGetSymbolAddress((void**)&chi, g_chi);
    cudaGetSymbolAddress((void**)&clo, g_clo);
    cudaGetSymbolAddress((void**)&wqh, g_wqthi);
    cudaGetSymbolAddress((void**)&wql, g_wqtlo);
    cudaGetSymbolAddress((void**)&wkh, g_wkthi);
    cudaGetSymbolAddress((void**)&wkl, g_wktlo);
    cudaGetSymbolAddress((void**)&wvh, g_wvthi);
    cudaGetSymbolAddress((void**)&wvl, g_wvtlo);
    cudaGetSymbolAddress((void**)&woh, g_wothi);
    cudaGetSymbolAddress((void**)&wol, g_wotlo);

    const int M = BB * TT;   // 4096

    // split x into bf16 hi/lo
    {
        long n4 = (long)M * DD / 4;
        split_kernel<<<(int)((n4 + 255) / 256), 256>>>(x, xhi, xlo, n4);
    }
    // transpose + split weights
    {
        dim3 blk(32, 32);
        transpose_split_kernel<<<dim3(DD / 32,  DD / 32), blk>>>(Wq, wqh, wql, DD, DD);
        transpose_split_kernel<<<dim3(KVD / 32, DD / 32), blk>>>(Wk, wkh, wkl, DD, KVD);
        transpose_split_kernel<<<dim3(KVD / 32, DD / 32), blk>>>(Wv, wvh, wvl, DD, KVD);
        transpose_split_kernel<<<dim3(DD / 32,  DD / 32), blk>>>(Wo, woh, wol, DD, DD);
    }

    // HMMA projections
    cudaFuncSetAttribute(hmma_gemm_kernel, cudaFuncAttributeMaxDynamicSharedMemorySize,
                         GEMM_SMEM);
    hmma_gemm_kernel<<<dim3(DD / 128,  M / 128, 1), 256, GEMM_SMEM>>>(
        xhi, xlo, wqh, wql, qb, DD, DD, 0, 0);
    hmma_gemm_kernel<<<dim3(KVD / 128, M / 128, 1), 256, GEMM_SMEM>>>(
        xhi, xlo, wkh, wkl, kb, KVD, DD, 0, 0);
    hmma_gemm_kernel<<<dim3(KVD / 128, M / 128, 1), 256, GEMM_SMEM>>>(
        xhi, xlo, wvh, wvl, vb, KVD, DD, 0, 0);

    // RoPE
    {
        long qPairs = (long)BB * TT * HH * (HDIM / 2);
        long kPairs = (long)BB * TT * GG * (HDIM / 2);
        rope_kernel<<<(int)((qPairs + 255) / 256), 256>>>(qb, HH, qPairs);
        rope_kernel<<<(int)((kPairs + 255) / 256), 256>>>(kb, GG, kPairs);
    }

    // Attention
    {
        int smemBytes = (2 * KTILE * HDIM + KTILE * QTILE) * (int)sizeof(float); // 64KB
        cudaFuncSetAttribute(attn_kernel, cudaFuncAttributeMaxDynamicSharedMemorySize,
                             smemBytes);
        attn_kernel<<<dim3(TT / QTILE, HH, BB), QTILE, smemBytes>>>(qb, kb, vb, ctxT);
    }

    // split ctxT, then final projection per batch: out[b] = ctxT[b] @ Wo
    {
        long n4 = (long)BB * DD * TT / 4;
        split_kernel<<<(int)((n4 + 255) / 256), 256>>>(ctxT, chi, clo, n4);
    }
    hmma_gemm_kernel<<<dim3(DD / 128, DD / 128, BB), 256, GEMM_SMEM>>>(
        chi, clo, woh, wol, out, DD, DD, (long)DD * TT, (long)TT * DD);
}

// round 5
// speedup vs baseline: 3.7242x; 2.1829x over previous
#include <cuda_runtime.h>
#include <cuda_bf16.h>
#include <math.h>
#include <stdint.h>

#define BB 2
#define TT 2048
#define DD 2048
#define HH 32
#define GG 8
#define HDIM 64
#define GROUPSZ 4
#define KVD (GG*HDIM)   // 512

// ---------------------------------------------------------------------------
// Scratch (__device__ globals; no allocations allowed)
// ---------------------------------------------------------------------------
__device__ float g_q[(size_t)BB*TT*HH*HDIM];     // [b][h][t][64] fp32 (head-major)
__device__ float g_k[(size_t)BB*TT*GG*HDIM];     // [b][g][t][64]
__device__ float g_v[(size_t)BB*TT*GG*HDIM];     // [b][g][t][64]

// bf16 hi/lo split buffers
__device__ __nv_bfloat16 g_xhi[(size_t)BB*TT*DD];
__device__ __nv_bfloat16 g_xlo[(size_t)BB*TT*DD];
__device__ __nv_bfloat16 g_qhi[(size_t)BB*TT*HH*HDIM];
__device__ __nv_bfloat16 g_qlo[(size_t)BB*TT*HH*HDIM];
__device__ __nv_bfloat16 g_khi[(size_t)BB*TT*GG*HDIM];
__device__ __nv_bfloat16 g_klo[(size_t)BB*TT*GG*HDIM];
__device__ __nv_bfloat16 g_vhi[(size_t)BB*TT*GG*HDIM];
__device__ __nv_bfloat16 g_vlo[(size_t)BB*TT*GG*HDIM];
__device__ __nv_bfloat16 g_chi[(size_t)BB*DD*TT];   // ctx^T hi [b][d][t]
__device__ __nv_bfloat16 g_clo[(size_t)BB*DD*TT];
// transposed weights [N][K]
__device__ __nv_bfloat16 g_wqthi[(size_t)DD*DD];
__device__ __nv_bfloat16 g_wqtlo[(size_t)DD*DD];
__device__ __nv_bfloat16 g_wkthi[(size_t)KVD*DD];
__device__ __nv_bfloat16 g_wktlo[(size_t)KVD*DD];
__device__ __nv_bfloat16 g_wvthi[(size_t)KVD*DD];
__device__ __nv_bfloat16 g_wvtlo[(size_t)KVD*DD];
__device__ __nv_bfloat16 g_wothi[(size_t)DD*DD];
__device__ __nv_bfloat16 g_wotlo[(size_t)DD*DD];

// ---------------------------------------------------------------------------
// PTX helpers (sm_80-era: cp.async + ldmatrix + mma.sync — valid on sm_103)
// ---------------------------------------------------------------------------
__device__ __forceinline__ uint32_t smem_to_u32(const void* p) {
    uint32_t a;
    asm("{ .reg .u64 tmp; cvta.to.shared.u64 tmp, %1; cvt.u32.u64 %0, tmp; }"
        : "=r"(a) : "l"(p));
    return a;
}
__device__ __forceinline__ void cp_async16(uint32_t dst, const void* src) {
    asm volatile("cp.async.cg.shared.global [%0], [%1], 16;" :: "r"(dst), "l"(src));
}
__device__ __forceinline__ void cp_commit() {
    asm volatile("cp.async.commit_group;" ::: "memory");
}
template <int N> __device__ __forceinline__ void cp_wait() {
    asm volatile("cp.async.wait_group %0;" :: "n"(N) : "memory");
}
__device__ __forceinline__ void ldsm_x4(uint32_t r[4], uint32_t addr) {
    asm volatile("ldmatrix.sync.aligned.m8n8.x4.shared.b16 {%0,%1,%2,%3}, [%4];"
                 : "=r"(r[0]), "=r"(r[1]), "=r"(r[2]), "=r"(r[3]) : "r"(addr));
}
__device__ __forceinline__ void ldsm_x4_t(uint32_t r[4], uint32_t addr) {
    asm volatile("ldmatrix.sync.aligned.m8n8.x4.trans.shared.b16 {%0,%1,%2,%3}, [%4];"
                 : "=r"(r[0]), "=r"(r[1]), "=r"(r[2]), "=r"(r[3]) : "r"(addr));
}
__device__ __forceinline__ void mma_bf16(float c[4], const uint32_t a[4],
                                         const uint32_t b0, const uint32_t b1) {
    asm volatile(
        "mma.sync.aligned.m16n8k16.row.col.f32.bf16.bf16.f32 "
        "{%0,%1,%2,%3}, {%4,%5,%6,%7}, {%8,%9}, {%0,%1,%2,%3};"
        : "+f"(c[0]), "+f"(c[1]), "+f"(c[2]), "+f"(c[3])
        : "r"(a[0]), "r"(a[1]), "r"(a[2]), "r"(a[3]), "r"(b0), "r"(b1));
}
__device__ __forceinline__ uint32_t pkbf2(__nv_bfloat16 a, __nv_bfloat16 b) {
    __nv_bfloat162 t(a, b);
    return *reinterpret_cast<uint32_t*>(&t);
}

// ---------------------------------------------------------------------------
// bf16 hi/lo split of a float array (layout agnostic)
// ---------------------------------------------------------------------------
__global__ void split_kernel(const float* __restrict__ in,
                             __nv_bfloat16* __restrict__ hi,
                             __nv_bfloat16* __restrict__ lo, long n4)
{
    long i = (long)blockIdx.x * blockDim.x + threadIdx.x;
    if (i >= n4) return;
    float4 v = ((const float4*)in)[i];
    __nv_bfloat16 h0 = __float2bfloat16(v.x);
    __nv_bfloat16 h1 = __float2bfloat16(v.y);
    __nv_bfloat16 h2 = __float2bfloat16(v.z);
    __nv_bfloat16 h3 = __float2bfloat16(v.w);
    ((__nv_bfloat162*)hi)[i * 2 + 0] = __nv_bfloat162(h0, h1);
    ((__nv_bfloat162*)hi)[i * 2 + 1] = __nv_bfloat162(h2, h3);
    ((__nv_bfloat162*)lo)[i * 2 + 0] =
        __nv_bfloat162(__float2bfloat16(v.x - __bfloat162float(h0)),
                       __float2bfloat16(v.y - __bfloat162float(h1)));
    ((__nv_bfloat162*)lo)[i * 2 + 1] =
        __nv_bfloat162(__float2bfloat16(v.z - __bfloat162float(h2)),
                       __float2bfloat16(v.w - __bfloat162float(h3)));
}

// ---------------------------------------------------------------------------
// RoPE + hi/lo split.  src fp32 [b][nh][t][64] head-major; pairs (d, d+32).
// ---------------------------------------------------------------------------
__global__ void rope_split_kernel(const float* __restrict__ src,
                                  __nv_bfloat16* __restrict__ hi,
                                  __nv_bfloat16* __restrict__ lo,
                                  float scale, long totalPairs)
{
    long idx = (long)blockIdx.x * blockDim.x + threadIdx.x;
    if (idx >= totalPairs) return;
    int d = (int)(idx & 31);
    long u = idx >> 5;
    int t = (int)(u & (TT - 1));

    float e = (float)d * (2.0f / (float)HDIM);
    float inv = 1.0f / powf(10000.0f, e);
    float ang = (float)t * inv;
    float s, c;
    sincosf(ang, &s, &c);

    size_t base = (size_t)u * 64 + d;
    float x1 = src[base];
    float x2 = src[base + 32];
    float y1 = (x1 * c - x2 * s) * scale;
    float y2 = (x2 * c + x1 * s) * scale;
    __nv_bfloat16 h1 = __float2bfloat16(y1);
    __nv_bfloat16 h2 = __float2bfloat16(y2);
    hi[base]      = h1;
    hi[base + 32] = h2;
    lo[base]      = __float2bfloat16(y1 - __bfloat162float(h1));
    lo[base + 32] = __float2bfloat16(y2 - __bfloat162float(h2));
}

// ---------------------------------------------------------------------------
// Transpose + split: W [K,N] fp32 -> Wt hi/lo [N,K] bf16
// ---------------------------------------------------------------------------
__global__ __launch_bounds__(1024) void transpose_split_kernel(
    const float* __restrict__ W,
    __nv_bfloat16* __restrict__ Thi, __nv_bfloat16* __restrict__ Tlo,
    int K, int N)
{
    __shared__ float tile[32][33];
    int tx = threadIdx.x, ty = threadIdx.y;
    int n0 = blockIdx.x * 32, k0 = blockIdx.y * 32;
    tile[ty][tx] = W[(long)(k0 + ty) * N + n0 + tx];
    __syncthreads();
    float v = tile[tx][ty];
    __nv_bfloat16 h = __float2bfloat16(v);
    __nv_bfloat16 l = __float2bfloat16(v - __bfloat162float(h));
    long oidx = (long)(n0 + ty) * K + k0 + tx;
    Thi[oidx] = h;
    Tlo[oidx] = l;
}

// ---------------------------------------------------------------------------
// HMMA GEMM: C[m][n] = sum_k A[m][k]*B[n][k]  (B pre-transposed, [N][K])
// bf16 hi/lo 3-term split.  headMajor=1 stores C as [b][n/64][t][64].
// ---------------------------------------------------------------------------
#define GM_TILE 128
#define KC      64
#define TILEB   (GM_TILE * KC * 2)      // 16384 bytes per tile
#define STAGEB  (4 * TILEB)             // Ah,Al,Bh,Bl = 64KB
#define GEMM_SMEM (2 * STAGEB)          // 128KB

__global__ __launch_bounds__(256, 1)
void hmma_gemm_kernel(const __nv_bfloat16* __restrict__ Ahi,
                      const __nv_bfloat16* __restrict__ Alo,
                      const __nv_bfloat16* __restrict__ Bhi,
                      const __nv_bfloat16* __restrict__ Blo,
                      float* __restrict__ C, int N, int K,
                      long aBatchStride, long cBatchStride, int headMajor)
{
    extern __shared__ __align__(128) char smem[];
    const uint32_t smem_base = smem_to_u32(smem);
    const int tid = threadIdx.x;
    const int wid = tid >> 5;
    const int lid = tid & 31;

    Ahi += (long)blockIdx.z * aBatchStride;
    Alo += (long)blockIdx.z * aBatchStride;
    C   += (long)blockIdx.z * cBatchStride;

    const int row0 = blockIdx.y * GM_TILE;
    const int col0 = blockIdx.x * GM_TILE;
    const int Rw = (wid >> 2) * 64;
    const int Cw = (wid & 3) * 32;

    float acc[4][4][4];
#pragma unroll
    for (int i = 0; i < 4; i++)
#pragma unroll
        for (int j = 0; j < 4; j++)
#pragma unroll
            for (int r = 0; r < 4; r++) acc[i][j][r] = 0.f;

    const int aMat  = lid >> 3;
    const int aRow  = ((aMat & 1) << 3) + (lid & 7);
    const int aCAdd = aMat >> 1;
    const int bRow  = ((lid >> 4) << 3) + (lid & 7);
    const int bCAdd = (lid >> 3) & 1;
    const int sw    = lid & 7;

    const int nch = K / KC;

    auto load_stage = [&](int buf, int k0) {
        const __nv_bfloat16* srcs[4] = {Ahi, Alo, Bhi, Blo};
        uint32_t stage = smem_base + buf * STAGEB;
#pragma unroll
        for (int t = 0; t < 4; t++) {
            const __nv_bfloat16* base = srcs[t];
            const int r0 = (t < 2) ? row0 : col0;
            uint32_t tileBase = stage + t * TILEB;
#pragma unroll
            for (int i = 0; i < 4; i++) {
                int e = i * 256 + tid;
                int r = e >> 3;
                int c = e & 7;
                uint32_t dst = tileBase + r * 128 + ((c ^ (r & 7)) << 4);
                cp_async16(dst, base + (size_t)(r0 + r) * K + k0 + c * 8);
            }
        }
        cp_commit();
    };

    load_stage(0, 0);

    for (int ch = 0; ch < nch; ch++) {
        if (ch + 1 < nch) {
            load_stage((ch + 1) & 1, (ch + 1) * KC);
            cp_wait<1>();
        } else {
            cp_wait<0>();
        }
        __syncthreads();

        uint32_t stage = smem_base + (ch & 1) * STAGEB;
        uint32_t tAh = stage + 0 * TILEB;
        uint32_t tAl = stage + 1 * TILEB;
        uint32_t tBh = stage + 2 * TILEB;
        uint32_t tBl = stage + 3 * TILEB;

#pragma unroll
        for (int ks = 0; ks < KC / 16; ks++) {
            uint32_t ah[4][4], al[4][4], bh[4][2], bl[4][2];
            const int c16 = ks * 2;
#pragma unroll
            for (int mf = 0; mf < 4; mf++) {
                int r = Rw + mf * 16 + aRow;
                uint32_t off = r * 128 + (((c16 + aCAdd) ^ sw) << 4);
                ldsm_x4(ah[mf], tAh + off);
                ldsm_x4(al[mf], tAl + off);
            }
#pragma unroll
            for (int np = 0; np < 2; np++) {
                int r = Cw + np * 16 + bRow;
                uint32_t off = r * 128 + (((c16 + bCAdd) ^ sw) << 4);
                uint32_t t4[4];
                ldsm_x4(t4, tBh + off);
                bh[np * 2][0] = t4[0]; bh[np * 2][1] = t4[1];
                bh[np * 2 + 1][0] = t4[2]; bh[np * 2 + 1][1] = t4[3];
                ldsm_x4(t4, tBl + off);
                bl[np * 2][0] = t4[0]; bl[np * 2][1] = t4[1];
                bl[np * 2 + 1][0] = t4[2]; bl[np * 2 + 1][1] = t4[3];
            }
#pragma unroll
            for (int mf = 0; mf < 4; mf++)
#pragma unroll
                for (int nf = 0; nf < 4; nf++)
                    mma_bf16(acc[mf][nf], ah[mf], bh[nf][0], bh[nf][1]);
#pragma unroll
            for (int mf = 0; mf < 4; mf++)
#pragma unroll
                for (int nf = 0; nf < 4; nf++)
                    mma_bf16(acc[mf][nf], al[mf], bh[nf][0], bh[nf][1]);
#pragma unroll
            for (int mf = 0; mf < 4; mf++)
#pragma unroll
                for (int nf = 0; nf < 4; nf++)
                    mma_bf16(acc[mf][nf], ah[mf], bl[nf][0], bl[nf][1]);
        }
        __syncthreads();
    }

    // epilogue
    float* stage = (float*)smem;
    const int g  = lid >> 2;
    const int tg = lid & 3;
#pragma unroll
    for (int mf = 0; mf < 4; mf++)
#pragma unroll
        for (int nf = 0; nf < 4; nf++) {
            int row = Rw + mf * 16 + g;
            int col = Cw + nf * 8 + 2 * tg;
            stage[row * 132 + col]           = acc[mf][nf][0];
            stage[row * 132 + col + 1]       = acc[mf][nf][1];
            stage[(row + 8) * 132 + col]     = acc[mf][nf][2];
            stage[(row + 8) * 132 + col + 1] = acc[mf][nf][3];
        }
    __syncthreads();
#pragma unroll
    for (int i = 0; i < 16; i++) {
        int e = i * 256 + tid;          // 0..4095 float4 slots
        int r = e >> 5;
        int c4 = e & 31;
        float4 v = *(float4*)&stage[r * 132 + c4 * 4];
        if (headMajor) {
            int m = row0 + r;                 // global row = b*T + t
            int bb = m >> 11;
            int t = m & (TT - 1);
            int col = col0 + c4 * 4;
            size_t dst = (((size_t)bb * (N >> 6) + (col >> 6)) * TT + t) * 64 + (col & 63);
            *(float4*)&C[dst] = v;
        } else {
            *(float4*)&C[(size_t)(row0 + r) * N + col0 + c4 * 4] = v;
        }
    }
}

// ---------------------------------------------------------------------------
// HMMA flash attention (causal, GQA).  CTA = 128 q-rows x (h,b); 8 warps x 16.
// Q hi/lo frags in regs; K/V hi/lo tiles (64 keys) double-buffered in smem.
// S = Qh Kh + Ql Kh + Qh Kl; P split hi/lo in regs; O += Ph Vh + Pl Vh + Ph Vl.
// Writes chi/clo [b][h*64+hd][t] bf16 hi/lo directly.
// ---------------------------------------------------------------------------
#define ATT_SMEM 65536

__global__ __launch_bounds__(256, 1) void attn_hmma_kernel(
    const __nv_bfloat16* __restrict__ qhi, const __nv_bfloat16* __restrict__ qlo,
    const __nv_bfloat16* __restrict__ khi, const __nv_bfloat16* __restrict__ klo,
    const __nv_bfloat16* __restrict__ vhi, const __nv_bfloat16* __restrict__ vlo,
    __nv_bfloat16* __restrict__ chi, __nv_bfloat16* __restrict__ clo)
{
    extern __shared__ __align__(128) char smem[];
    const uint32_t sb = smem_to_u32(smem);
    const int tid = threadIdx.x, wid = tid >> 5, lid = tid & 31;
    const int qt = blockIdx.x, h = blockIdx.y, b = blockIdx.z;
    const int g = h / GROUPSZ;
    const int tg = lid & 3, gr = lid >> 2;

    const size_t qoff   = ((size_t)(b * HH + h) * TT + (size_t)qt * 128) * 64;
    const size_t kvoff0 = ((size_t)(b * GG + g) * TT) * 64;

    auto kv_load = [&](int buf, int kt) {
        const __nv_bfloat16* srcs[4] = {
            khi + kvoff0 + (size_t)kt * 64 * 64,
            klo + kvoff0 + (size_t)kt * 64 * 64,
            vhi + kvoff0 + (size_t)kt * 64 * 64,
            vlo + kvoff0 + (size_t)kt * 64 * 64 };
        uint32_t bbase = sb + buf * 32768;
#pragma unroll
        for (int i = 0; i < 8; i++) {
            int e = i * 256 + tid;
            int part = e >> 9, rr = (e >> 3) & 63, c = e & 7;
            cp_async16(bbase + part * 8192 + rr * 128 + ((c ^ (rr & 7)) << 4),
                       srcs[part] + (size_t)rr * 64 + c * 8);
        }
        cp_commit();
    };

    // Q tiles (hi at buf0+0, lo at buf0+16K) + KV tile 0 (buf1), one group
#pragma unroll
    for (int i = 0; i < 8; i++) {
        int e = i * 256 + tid;
        int part = e >> 10, rr = (e >> 3) & 127, c = e & 7;
        const __nv_bfloat16* s = (part ? qlo : qhi) + qoff;
        cp_async16(sb + part * 16384 + rr * 128 + ((c ^ (rr & 7)) << 4),
                   s + (size_t)rr * 64 + c * 8);
    }
    kv_load(1, 0);
    cp_wait<0>();
    __syncthreads();

    // extract Q fragments (kept in regs for the whole kernel)
    uint32_t qhf[4][4], qlf[4][4];
    {
        const int aMat = lid >> 3;
        const int aRow = ((aMat & 1) << 3) + (lid & 7);
        const int aCAdd = aMat >> 1;
#pragma unroll
        for (int kf = 0; kf < 4; kf++) {
            int r = wid * 16 + aRow;
            uint32_t off = r * 128 + (((2 * kf + aCAdd) ^ (r & 7)) << 4);
            ldsm_x4(qhf[kf], sb + off);
            ldsm_x4(qlf[kf], sb + 16384 + off);
        }
    }
    __syncthreads();

    float O[8][4];
#pragma unroll
    for (int nf = 0; nf < 8; nf++)
#pragma unroll
        for (int r = 0; r < 4; r++) O[nf][r] = 0.f;
    float m0 = -INFINITY, m1 = -INFINITY, l0 = 0.f, l1 = 0.f;

    const int nkt = 2 * qt + 2;
    const int bRow = ((lid >> 4) << 3) + (lid & 7);
    const int bCAdd = (lid >> 3) & 1;

    for (int kt = 0; kt < nkt; kt++) {
        if (kt + 1 < nkt) { kv_load(kt & 1, kt + 1); cp_wait<1>(); }
        else              { cp_wait<0>(); }
        __syncthreads();
        const uint32_t kv = sb + ((kt + 1) & 1) * 32768;

        // ---- S = Q K^T (3 passes) ----
        float S[8][4];
#pragma unroll
        for (int nf = 0; nf < 8; nf++)
#pragma unroll
            for (int r = 0; r < 4; r++) S[nf][r] = 0.f;

#pragma unroll
        for (int ks = 0; ks < 4; ks++) {
            uint32_t khf[4][4], klf[4][4];
#pragma unroll
            for (int np = 0; np < 4; np++) {
                int r = np * 16 + bRow;
                uint32_t off = r * 128 + (((2 * ks + bCAdd) ^ (r & 7)) << 4);
                ldsm_x4(khf[np], kv + off);
                ldsm_x4(klf[np], kv + 8192 + off);
            }
#pragma unroll
            for (int np = 0; np < 4; np++)
#pragma unroll
                for (int hf2 = 0; hf2 < 2; hf2++) {
                    int nf = np * 2 + hf2;
                    mma_bf16(S[nf], qhf[ks], khf[np][2 * hf2], khf[np][2 * hf2 + 1]);
                    mma_bf16(S[nf], qlf[ks], khf[np][2 * hf2], khf[np][2 * hf2 + 1]);
                    mma_bf16(S[nf], qhf[ks], klf[np][2 * hf2], klf[np][2 * hf2 + 1]);
                }
        }

        // ---- causal mask ----
        const int row0 = qt * 128 + wid * 16 + gr;
        if (kt * 64 + 63 > row0) {
#pragma unroll
            for (int nf = 0; nf < 8; nf++) {
                int colb = kt * 64 + 8 * nf + 2 * tg;
                if (colb     > row0)     S[nf][0] = -INFINITY;
                if (colb + 1 > row0)     S[nf][1] = -INFINITY;
                if (colb     > row0 + 8) S[nf][2] = -INFINITY;
                if (colb + 1 > row0 + 8) S[nf][3] = -INFINITY;
            }
        }

        // ---- online softmax ----
        float mt0 = m0, mt1 = m1;
#pragma unroll
        for (int nf = 0; nf < 8; nf++) {
            mt0 = fmaxf(mt0, fmaxf(S[nf][0], S[nf][1]));
            mt1 = fmaxf(mt1, fmaxf(S[nf][2], S[nf][3]));
        }
        mt0 = fmaxf(mt0, __shfl_xor_sync(0xffffffffu, mt0, 1));
        mt0 = fmaxf(mt0, __shfl_xor_sync(0xffffffffu, mt0, 2));
        mt1 = fmaxf(mt1, __shfl_xor_sync(0xffffffffu, mt1, 1));
        mt1 = fmaxf(mt1, __shfl_xor_sync(0xffffffffu, mt1, 2));
        float c0 = __expf(m0 - mt0), c1 = __expf(m1 - mt1);
        m0 = mt0; m1 = mt1;
        float ls0 = 0.f, ls1 = 0.f;
#pragma unroll
        for (int nf = 0; nf < 8; nf++) {
            S[nf][0] = __expf(S[nf][0] - mt0); ls0 += S[nf][0];
            S[nf][1] = __expf(S[nf][1] - mt0); ls0 += S[nf][1];
            S[nf][2] = __expf(S[nf][2] - mt1); ls1 += S[nf][2];
            S[nf][3] = __expf(S[nf][3] - mt1); ls1 += S[nf][3];
        }
        l0 = l0 * c0 + ls0;
        l1 = l1 * c1 + ls1;
#pragma unroll
        for (int nf = 0; nf < 8; nf++) {
            O[nf][0] *= c0; O[nf][1] *= c0; O[nf][2] *= c1; O[nf][3] *= c1;
        }

        // ---- O += P V (3 passes) ----
#pragma unroll
        for (int ks = 0; ks < 4; ks++) {
            uint32_t pah[4], pal[4];
            {
                float p[8] = { S[2*ks][0], S[2*ks][1], S[2*ks][2], S[2*ks][3],
                               S[2*ks+1][0], S[2*ks+1][1], S[2*ks+1][2], S[2*ks+1][3] };
                __nv_bfloat16 hh[8], ll[8];
#pragma unroll
                for (int j = 0; j < 8; j++) {
                    hh[j] = __float2bfloat16(p[j]);
                    ll[j] = __float2bfloat16(p[j] - __bfloat162float(hh[j]));
                }
                pah[0] = pkbf2(hh[0], hh[1]); pah[1] = pkbf2(hh[2], hh[3]);
                pah[2] = pkbf2(hh[4], hh[5]); pah[3] = pkbf2(hh[6], hh[7]);
                pal[0] = pkbf2(ll[0], ll[1]); pal[1] = pkbf2(ll[2], ll[3]);
                pal[2] = pkbf2(ll[4], ll[5]); pal[3] = pkbf2(ll[6], ll[7]);
            }
            uint32_t vhf[4][4], vlf[4][4];
            {
                int blk = lid >> 3;
                int r = ks * 16 + ((blk & 1) << 3) + (lid & 7);
#pragma unroll
                for (int np = 0; np < 4; np++) {
                    int chunk = 2 * np + (blk >> 1);
                    uint32_t off = r * 128 + ((chunk ^ (r & 7)) << 4);
                    ldsm_x4_t(vhf[np], kv + 16384 + off);
                    ldsm_x4_t(vlf[np], kv + 24576 + off);
                }
            }
#pragma unroll
            for (int np = 0; np < 4; np++)
#pragma unroll
                for (int hf2 = 0; hf2 < 2; hf2++) {
                    int nf = np * 2 + hf2;
                    mma_bf16(O[nf], pah, vhf[np][2 * hf2], vhf[np][2 * hf2 + 1]);
                    mma_bf16(O[nf], pal, vhf[np][2 * hf2], vhf[np][2 * hf2 + 1]);
                    mma_bf16(O[nf], pah, vlf[np][2 * hf2], vlf[np][2 * hf2 + 1]);
                }
        }
        __syncthreads();
    }

    // ---- epilogue ----
    l0 += __shfl_xor_sync(0xffffffffu, l0, 1);
    l0 += __shfl_xor_sync(0xffffffffu, l0, 2);
    l1 += __shfl_xor_sync(0xffffffffu, l1, 1);
    l1 += __shfl_xor_sync(0xffffffffu, l1, 2);
    const float i0 = 1.f / l0, i1 = 1.f / l1;

    float* stg = (float*)smem;          // [64 hd][132]
#pragma unroll
    for (int nf = 0; nf < 8; nf++) {
        int c = 8 * nf + 2 * tg;
        int q0 = wid * 16 + gr;
        stg[c * 132 + q0]           = O[nf][0] * i0;
        stg[(c + 1) * 132 + q0]     = O[nf][1] * i0;
        stg[c * 132 + q0 + 8]       = O[nf][2] * i1;
        stg[(c + 1) * 132 + q0 + 8] = O[nf][3] * i1;
    }
    __syncthreads();

    const size_t ob = ((size_t)b * DD + (size_t)h * 64) * TT + (size_t)qt * 128;
#pragma unroll
    for (int i = 0; i < 8; i++) {
        int e = i * 256 + tid;          // 64 cols x 32 float4
        int c = e >> 5;
        int q4 = e & 31;
        float4 v = *(float4*)&stg[c * 132 + q4 * 4];
        __nv_bfloat16 h0 = __float2bfloat16(v.x), h1 = __float2bfloat16(v.y);
        __nv_bfloat16 h2 = __float2bfloat16(v.z), h3 = __float2bfloat16(v.w);
        uint2 hv, lv;
        hv.x = pkbf2(h0, h1); hv.y = pkbf2(h2, h3);
        lv.x = pkbf2(__float2bfloat16(v.x - __bfloat162float(h0)),
                     __float2bfloat16(v.y - __bfloat162float(h1)));
        lv.y = pkbf2(__float2bfloat16(v.z - __bfloat162float(h2)),
                     __float2bfloat16(v.w - __bfloat162float(h3)));
        size_t dst = ob + (size_t)c * TT + q4 * 4;
        *(uint2*)&chi[dst] = hv;
        *(uint2*)&clo[dst] = lv;
    }
}

// ---------------------------------------------------------------------------
// Launch
// ---------------------------------------------------------------------------
extern "C" void kernel_launch(void* const* d_in, const int* in_sizes, int n_in,
                              void* d_out, int out_size)
{
    const float* x  = (const float*)d_in[0];
    const float* Wq = (const float*)d_in[1];
    const float* Wk = (const float*)d_in[2];
    const float* Wv = (const float*)d_in[3];
    const float* Wo = (const float*)d_in[4];
    float* out = (float*)d_out;

    float *qb, *kb, *vb;
    cudaGetSymbolAddress((void**)&qb, g_q);
    cudaGetSymbolAddress((void**)&kb, g_k);
    cudaGetSymbolAddress((void**)&vb, g_v);
    __nv_bfloat16 *xhi, *xlo, *chi, *clo, *qhi, *qlo, *khi, *klo, *vhi, *vlo;
    __nv_bfloat16 *wqh, *wql, *wkh, *wkl, *wvh, *wvl, *woh, *wol;
    cudaGetSymbolAddress((void**)&xhi, g_xhi);
    cudaGetSymbolAddress((void**)&xlo, g_xlo);
    cudaGetSymbolAddress((void**)&chi, g_chi);
    cudaGetSymbolAddress((void**)&clo, g_clo);
    cudaGetSymbolAddress((void**)&qhi, g_qhi);
    cudaGetSymbolAddress((void**)&qlo, g_qlo);
    cudaGetSymbolAddress((void**)&khi, g_khi);
    cudaGetSymbolAddress((void**)&klo, g_klo);
    cudaGetSymbolAddress((void**)&vhi, g_vhi);
    cudaGetSymbolAddress((void**)&vlo, g_vlo);
    cudaGetSymbolAddress((void**)&wqh, g_wqthi);
    cudaGetSymbolAddress((void**)&wql, g_wqtlo);
    cudaGetSymbolAddress((void**)&wkh, g_wkthi);
    cudaGetSymbolAddress((void**)&wkl, g_wktlo);
    cudaGetSymbolAddress((void**)&wvh, g_wvthi);
    cudaGetSymbolAddress((void**)&wvl, g_wvtlo);
    cudaGetSymbolAddress((void**)&woh, g_wothi);
    cudaGetSymbolAddress((void**)&wol, g_wotlo);

    const int M = BB * TT;   // 4096

    // split x into bf16 hi/lo
    {
        long n4 = (long)M * DD / 4;
        split_kernel<<<(int)((n4 + 255) / 256), 256>>>(x, xhi, xlo, n4);
    }
    // transpose + split weights
    {
        dim3 blk(32, 32);
        transpose_split_kernel<<<dim3(DD / 32,  DD / 32), blk>>>(Wq, wqh, wql, DD, DD);
        transpose_split_kernel<<<dim3(KVD / 32, DD / 32), blk>>>(Wk, wkh, wkl, DD, KVD);
        transpose_split_kernel<<<dim3(KVD / 32, DD / 32), blk>>>(Wv, wvh, wvl, DD, KVD);
        transpose_split_kernel<<<dim3(DD / 32,  DD / 32), blk>>>(Wo, woh, wol, DD, DD);
    }

    // HMMA projections, head-major fp32 outputs
    cudaFuncSetAttribute(hmma_gemm_kernel, cudaFuncAttributeMaxDynamicSharedMemorySize,
                         GEMM_SMEM);
    hmma_gemm_kernel<<<dim3(DD / 128,  M / 128, 1), 256, GEMM_SMEM>>>(
        xhi, xlo, wqh, wql, qb, DD, DD, 0, 0, 1);
    hmma_gemm_kernel<<<dim3(KVD / 128, M / 128, 1), 256, GEMM_SMEM>>>(
        xhi, xlo, wkh, wkl, kb, KVD, DD, 0, 0, 1);
    hmma_gemm_kernel<<<dim3(KVD / 128, M / 128, 1), 256, GEMM_SMEM>>>(
        xhi, xlo, wvh, wvl, vb, KVD, DD, 0, 0, 1);

    // RoPE + split (q scaled by 1/sqrt(64)); plain split for v
    {
        long qPairs = (long)BB * HH * TT * 32;
        long kPairs = (long)BB * GG * TT * 32;
        rope_split_kernel<<<(int)((qPairs + 255) / 256), 256>>>(qb, qhi, qlo, 0.125f, qPairs);
        rope_split_kernel<<<(int)((kPairs + 255) / 256), 256>>>(kb, khi, klo, 1.0f, kPairs);
        long v4 = (long)BB * GG * TT * 64 / 4;
        split_kernel<<<(int)((v4 + 255) / 256), 256>>>(vb, vhi, vlo, v4);
    }

    // HMMA flash attention -> chi/clo
    cudaFuncSetAttribute(attn_hmma_kernel, cudaFuncAttributeMaxDynamicSharedMemorySize,
                         ATT_SMEM);
    attn_hmma_kernel<<<dim3(TT / 128, HH, BB), 256, ATT_SMEM>>>(
        qhi, qlo, khi, klo, vhi, vlo, chi, clo);

    // final projection: out[b] = ctxT[b] @ Wo
    hmma_gemm_kernel<<<dim3(DD / 128, DD / 128, BB), 256, GEMM_SMEM>>>(
        chi, clo, woh, wol, out, DD, DD, (long)DD * TT, (long)TT * DD, 0);
}

// round 6
// speedup vs baseline: 3.7545x; 1.0081x over previous
#include <cuda_runtime.h>
#include <cuda_bf16.h>
#include <math.h>
#include <stdint.h>

#define BB 2
#define TT 2048
#define DD 2048
#define HH 32
#define GG 8
#define HDIM 64
#define GROUPSZ 4
#define KVD (GG*HDIM)   // 512
#define NQKV (DD + 2*KVD)   // 3072

// ---------------------------------------------------------------------------
// Scratch (__device__ globals; no allocations allowed)
// ---------------------------------------------------------------------------
__device__ float g_q[(size_t)BB*TT*HH*HDIM];     // [b][h][t][64] fp32 (head-major)
__device__ float g_k[(size_t)BB*TT*GG*HDIM];     // [b][g][t][64]
__device__ float g_v[(size_t)BB*TT*GG*HDIM];     // [b][g][t][64]

// bf16 hi/lo split buffers
__device__ __nv_bfloat16 g_xhi[(size_t)BB*TT*DD];
__device__ __nv_bfloat16 g_xlo[(size_t)BB*TT*DD];
__device__ __nv_bfloat16 g_qhi[(size_t)BB*TT*HH*HDIM];
__device__ __nv_bfloat16 g_qlo[(size_t)BB*TT*HH*HDIM];
__device__ __nv_bfloat16 g_khi[(size_t)BB*TT*GG*HDIM];
__device__ __nv_bfloat16 g_klo[(size_t)BB*TT*GG*HDIM];
__device__ __nv_bfloat16 g_vhi[(size_t)BB*TT*GG*HDIM];
__device__ __nv_bfloat16 g_vlo[(size_t)BB*TT*GG*HDIM];
__device__ __nv_bfloat16 g_chi[(size_t)BB*DD*TT];   // ctx^T hi [b][d][t]
__device__ __nv_bfloat16 g_clo[(size_t)BB*DD*TT];
// transposed weights [N][K]: fused QKV = rows [0,2048) Wq, [2048,2560) Wk, [2560,3072) Wv
__device__ __nv_bfloat16 g_wqkvhi[(size_t)NQKV*DD];
__device__ __nv_bfloat16 g_wqkvlo[(size_t)NQKV*DD];
__device__ __nv_bfloat16 g_wothi[(size_t)DD*DD];
__device__ __nv_bfloat16 g_wotlo[(size_t)DD*DD];

// ---------------------------------------------------------------------------
// PTX helpers (sm_80-era: cp.async + ldmatrix + mma.sync — valid on sm_103)
// ---------------------------------------------------------------------------
__device__ __forceinline__ uint32_t smem_to_u32(const void* p) {
    uint32_t a;
    asm("{ .reg .u64 tmp; cvta.to.shared.u64 tmp, %1; cvt.u32.u64 %0, tmp; }"
        : "=r"(a) : "l"(p));
    return a;
}
__device__ __forceinline__ void cp_async16(uint32_t dst, const void* src) {
    asm volatile("cp.async.cg.shared.global [%0], [%1], 16;" :: "r"(dst), "l"(src));
}
__device__ __forceinline__ void cp_commit() {
    asm volatile("cp.async.commit_group;" ::: "memory");
}
template <int N> __device__ __forceinline__ void cp_wait() {
    asm volatile("cp.async.wait_group %0;" :: "n"(N) : "memory");
}
__device__ __forceinline__ void ldsm_x4(uint32_t r[4], uint32_t addr) {
    asm volatile("ldmatrix.sync.aligned.m8n8.x4.shared.b16 {%0,%1,%2,%3}, [%4];"
                 : "=r"(r[0]), "=r"(r[1]), "=r"(r[2]), "=r"(r[3]) : "r"(addr));
}
__device__ __forceinline__ void ldsm_x4_t(uint32_t r[4], uint32_t addr) {
    asm volatile("ldmatrix.sync.aligned.m8n8.x4.trans.shared.b16 {%0,%1,%2,%3}, [%4];"
                 : "=r"(r[0]), "=r"(r[1]), "=r"(r[2]), "=r"(r[3]) : "r"(addr));
}
__device__ __forceinline__ void mma_bf16(float c[4], const uint32_t a[4],
                                         const uint32_t b0, const uint32_t b1) {
    asm volatile(
        "mma.sync.aligned.m16n8k16.row.col.f32.bf16.bf16.f32 "
        "{%0,%1,%2,%3}, {%4,%5,%6,%7}, {%8,%9}, {%0,%1,%2,%3};"
        : "+f"(c[0]), "+f"(c[1]), "+f"(c[2]), "+f"(c[3])
        : "r"(a[0]), "r"(a[1]), "r"(a[2]), "r"(a[3]), "r"(b0), "r"(b1));
}
__device__ __forceinline__ uint32_t pkbf2(__nv_bfloat16 a, __nv_bfloat16 b) {
    __nv_bfloat162 t(a, b);
    return *reinterpret_cast<uint32_t*>(&t);
}

// ---------------------------------------------------------------------------
// bf16 hi/lo split of a float array (layout agnostic)
// ---------------------------------------------------------------------------
__global__ void split_kernel(const float* __restrict__ in,
                             __nv_bfloat16* __restrict__ hi,
                             __nv_bfloat16* __restrict__ lo, long n4)
{
    long i = (long)blockIdx.x * blockDim.x + threadIdx.x;
    if (i >= n4) return;
    float4 v = ((const float4*)in)[i];
    __nv_bfloat16 h0 = __float2bfloat16(v.x);
    __nv_bfloat16 h1 = __float2bfloat16(v.y);
    __nv_bfloat16 h2 = __float2bfloat16(v.z);
    __nv_bfloat16 h3 = __float2bfloat16(v.w);
    ((__nv_bfloat162*)hi)[i * 2 + 0] = __nv_bfloat162(h0, h1);
    ((__nv_bfloat162*)hi)[i * 2 + 1] = __nv_bfloat162(h2, h3);
    ((__nv_bfloat162*)lo)[i * 2 + 0] =
        __nv_bfloat162(__float2bfloat16(v.x - __bfloat162float(h0)),
                       __float2bfloat16(v.y - __bfloat162float(h1)));
    ((__nv_bfloat162*)lo)[i * 2 + 1] =
        __nv_bfloat162(__float2bfloat16(v.z - __bfloat162float(h2)),
                       __float2bfloat16(v.w - __bfloat162float(h3)));
}

// ---------------------------------------------------------------------------
// Merged conversion: RoPE+split for q (scaled), RoPE+split for k, split for v.
// All buffers head-major [b][nh][t][64]; one thread = one (d, d+32) pair.
// ---------------------------------------------------------------------------
#define QPAIRS ((long)BB*HH*TT*32)
#define KPAIRS ((long)BB*GG*TT*32)
#define VPAIRS ((long)BB*GG*TT*32)

__global__ void convert_all_kernel(
    const float* __restrict__ qsrc, const float* __restrict__ ksrc,
    const float* __restrict__ vsrc,
    __nv_bfloat16* __restrict__ qhi, __nv_bfloat16* __restrict__ qlo,
    __nv_bfloat16* __restrict__ khi, __nv_bfloat16* __restrict__ klo,
    __nv_bfloat16* __restrict__ vhi, __nv_bfloat16* __restrict__ vlo)
{
    long idx = (long)blockIdx.x * blockDim.x + threadIdx.x;
    const float* src;
    __nv_bfloat16 *hi, *lo;
    float scale;
    int doRope;
    if (idx < QPAIRS) {
        src = qsrc; hi = qhi; lo = qlo; scale = 0.125f; doRope = 1;
    } else if (idx < QPAIRS + KPAIRS) {
        idx -= QPAIRS;
        src = ksrc; hi = khi; lo = klo; scale = 1.0f; doRope = 1;
    } else if (idx < QPAIRS + KPAIRS + VPAIRS) {
        idx -= QPAIRS + KPAIRS;
        src = vsrc; hi = vhi; lo = vlo; scale = 1.0f; doRope = 0;
    } else return;

    int d = (int)(idx & 31);
    long u = idx >> 5;
    size_t base = (size_t)u * 64 + d;
    float x1 = src[base];
    float x2 = src[base + 32];
    float y1, y2;
    if (doRope) {
        int t = (int)(u & (TT - 1));
        float e = (float)d * (2.0f / (float)HDIM);
        float inv = 1.0f / powf(10000.0f, e);
        float ang = (float)t * inv;
        float s, c;
        sincosf(ang, &s, &c);
        y1 = (x1 * c - x2 * s) * scale;
        y2 = (x2 * c + x1 * s) * scale;
    } else {
        y1 = x1; y2 = x2;
    }
    __nv_bfloat16 h1 = __float2bfloat16(y1);
    __nv_bfloat16 h2 = __float2bfloat16(y2);
    hi[base]      = h1;
    hi[base + 32] = h2;
    lo[base]      = __float2bfloat16(y1 - __bfloat162float(h1));
    lo[base + 32] = __float2bfloat16(y2 - __bfloat162float(h2));
}

// ---------------------------------------------------------------------------
// Transpose + split: W [K,N] fp32 -> Wt hi/lo [N,K] bf16 (dst may be offset)
// ---------------------------------------------------------------------------
__global__ __launch_bounds__(1024) void transpose_split_kernel(
    const float* __restrict__ W,
    __nv_bfloat16* __restrict__ Thi, __nv_bfloat16* __restrict__ Tlo,
    int K, int N)
{
    __shared__ float tile[32][33];
    int tx = threadIdx.x, ty = threadIdx.y;
    int n0 = blockIdx.x * 32, k0 = blockIdx.y * 32;
    tile[ty][tx] = W[(long)(k0 + ty) * N + n0 + tx];
    __syncthreads();
    float v = tile[tx][ty];
    __nv_bfloat16 h = __float2bfloat16(v);
    __nv_bfloat16 l = __float2bfloat16(v - __bfloat162float(h));
    long oidx = (long)(n0 + ty) * K + k0 + tx;
    Thi[oidx] = h;
    Tlo[oidx] = l;
}

// ---------------------------------------------------------------------------
// HMMA GEMM: C[m][n] = sum_k A[m][k]*B[n][k]  (B pre-transposed, [N][K])
// bf16 hi/lo 3-term split: D += Ah*Bh + Al*Bh + Ah*Bl.
// mode 0: plain row-major C.   mode 1: fused-QKV head-major scatter.
// ---------------------------------------------------------------------------
#define GM_TILE 128
#define KC      64
#define TILEB   (GM_TILE * KC * 2)      // 16384 bytes per tile
#define STAGEB  (4 * TILEB)             // Ah,Al,Bh,Bl = 64KB
#define GEMM_SMEM (2 * STAGEB)          // 128KB

__global__ __launch_bounds__(256, 1)
void hmma_gemm_kernel(const __nv_bfloat16* __restrict__ Ahi,
                      const __nv_bfloat16* __restrict__ Alo,
                      const __nv_bfloat16* __restrict__ Bhi,
                      const __nv_bfloat16* __restrict__ Blo,
                      float* __restrict__ C, float* __restrict__ Ck,
                      float* __restrict__ Cv, int N, int K,
                      long aBatchStride, long cBatchStride, int mode)
{
    extern __shared__ __align__(128) char smem[];
    const uint32_t smem_base = smem_to_u32(smem);
    const int tid = threadIdx.x;
    const int wid = tid >> 5;
    const int lid = tid & 31;

    Ahi += (long)blockIdx.z * aBatchStride;
    Alo += (long)blockIdx.z * aBatchStride;
    C   += (long)blockIdx.z * cBatchStride;

    const int row0 = blockIdx.y * GM_TILE;
    const int col0 = blockIdx.x * GM_TILE;
    const int Rw = (wid >> 2) * 64;
    const int Cw = (wid & 3) * 32;

    float acc[4][4][4];
#pragma unroll
    for (int i = 0; i < 4; i++)
#pragma unroll
        for (int j = 0; j < 4; j++)
#pragma unroll
            for (int r = 0; r < 4; r++) acc[i][j][r] = 0.f;

    const int aMat  = lid >> 3;
    const int aRow  = ((aMat & 1) << 3) + (lid & 7);
    const int aCAdd = aMat >> 1;
    const int bRow  = ((lid >> 4) << 3) + (lid & 7);
    const int bCAdd = (lid >> 3) & 1;
    const int sw    = lid & 7;

    const int nch = K / KC;

    auto load_stage = [&](int buf, int k0) {
        const __nv_bfloat16* srcs[4] = {Ahi, Alo, Bhi, Blo};
        uint32_t stage = smem_base + buf * STAGEB;
#pragma unroll
        for (int t = 0; t < 4; t++) {
            const __nv_bfloat16* base = srcs[t];
            const int r0 = (t < 2) ? row0 : col0;
            uint32_t tileBase = stage + t * TILEB;
#pragma unroll
            for (int i = 0; i < 4; i++) {
                int e = i * 256 + tid;
                int r = e >> 3;
                int c = e & 7;
                uint32_t dst = tileBase + r * 128 + ((c ^ (r & 7)) << 4);
                cp_async16(dst, base + (size_t)(r0 + r) * K + k0 + c * 8);
            }
        }
        cp_commit();
    };

    load_stage(0, 0);

    for (int ch = 0; ch < nch; ch++) {
        if (ch + 1 < nch) {
            load_stage((ch + 1) & 1, (ch + 1) * KC);
            cp_wait<1>();
        } else {
            cp_wait<0>();
        }
        __syncthreads();

        uint32_t stage = smem_base + (ch & 1) * STAGEB;
        uint32_t tAh = stage + 0 * TILEB;
        uint32_t tAl = stage + 1 * TILEB;
        uint32_t tBh = stage + 2 * TILEB;
        uint32_t tBl = stage + 3 * TILEB;

#pragma unroll
        for (int ks = 0; ks < KC / 16; ks++) {
            uint32_t ah[4][4], al[4][4], bh[4][2], bl[4][2];
            const int c16 = ks * 2;
#pragma unroll
            for (int mf = 0; mf < 4; mf++) {
                int r = Rw + mf * 16 + aRow;
                uint32_t off = r * 128 + (((c16 + aCAdd) ^ sw) << 4);
                ldsm_x4(ah[mf], tAh + off);
                ldsm_x4(al[mf], tAl + off);
            }
#pragma unroll
            for (int np = 0; np < 2; np++) {
                int r = Cw + np * 16 + bRow;
                uint32_t off = r * 128 + (((c16 + bCAdd) ^ sw) << 4);
                uint32_t t4[4];
                ldsm_x4(t4, tBh + off);
                bh[np * 2][0] = t4[0]; bh[np * 2][1] = t4[1];
                bh[np * 2 + 1][0] = t4[2]; bh[np * 2 + 1][1] = t4[3];
                ldsm_x4(t4, tBl + off);
                bl[np * 2][0] = t4[0]; bl[np * 2][1] = t4[1];
                bl[np * 2 + 1][0] = t4[2]; bl[np * 2 + 1][1] = t4[3];
            }
#pragma unroll
            for (int mf = 0; mf < 4; mf++)
#pragma unroll
                for (int nf = 0; nf < 4; nf++)
                    mma_bf16(acc[mf][nf], ah[mf], bh[nf][0], bh[nf][1]);
#pragma unroll
            for (int mf = 0; mf < 4; mf++)
#pragma unroll
                for (int nf = 0; nf < 4; nf++)
                    mma_bf16(acc[mf][nf], al[mf], bh[nf][0], bh[nf][1]);
#pragma unroll
            for (int mf = 0; mf < 4; mf++)
#pragma unroll
                for (int nf = 0; nf < 4; nf++)
                    mma_bf16(acc[mf][nf], ah[mf], bl[nf][0], bl[nf][1]);
        }
        __syncthreads();
    }

    // epilogue
    float* stage = (float*)smem;
    const int g  = lid >> 2;
    const int tg = lid & 3;
#pragma unroll
    for (int mf = 0; mf < 4; mf++)
#pragma unroll
        for (int nf = 0; nf < 4; nf++) {
            int row = Rw + mf * 16 + g;
            int col = Cw + nf * 8 + 2 * tg;
            stage[row * 132 + col]           = acc[mf][nf][0];
            stage[row * 132 + col + 1]       = acc[mf][nf][1];
            stage[(row + 8) * 132 + col]     = acc[mf][nf][2];
            stage[(row + 8) * 132 + col + 1] = acc[mf][nf][3];
        }
    __syncthreads();
#pragma unroll
    for (int i = 0; i < 16; i++) {
        int e = i * 256 + tid;          // 0..4095 float4 slots
        int r = e >> 5;
        int c4 = e & 31;
        float4 v = *(float4*)&stage[r * 132 + c4 * 4];
        if (mode == 1) {
            // fused QKV head-major scatter: rows = b*T+t, cols = qkv channel
            int m = row0 + r;
            int bb = m >> 11;
            int t = m & (TT - 1);
            int col = col0 + c4 * 4;
            float* dstBase;
            int head;
            if (col < DD)            { dstBase = C;  head = col >> 6;          }
            else if (col < DD + KVD) { dstBase = Ck; head = (col - DD) >> 6;   }
            else                     { dstBase = Cv; head = (col - DD - KVD) >> 6; }
            int nh = (dstBase == C) ? HH : GG;
            size_t dst = (((size_t)bb * nh + head) * TT + t) * 64 + (col & 63);
            *(float4*)&dstBase[dst] = v;
        } else {
            *(float4*)&C[(size_t)(row0 + r) * N + col0 + c4 * 4] = v;
        }
    }
}

// ---------------------------------------------------------------------------
// HMMA flash attention (causal, GQA).  CTA = 128 q-rows x (h,b); 8 warps x 16.
// qt reversed so heaviest CTAs schedule first.
// ---------------------------------------------------------------------------
#define ATT_SMEM 65536

__global__ __launch_bounds__(256, 1) void attn_hmma_kernel(
    const __nv_bfloat16* __restrict__ qhi, const __nv_bfloat16* __restrict__ qlo,
    const __nv_bfloat16* __restrict__ khi, const __nv_bfloat16* __restrict__ klo,
    const __nv_bfloat16* __restrict__ vhi, const __nv_bfloat16* __restrict__ vlo,
    __nv_bfloat16* __restrict__ chi, __nv_bfloat16* __restrict__ clo)
{
    extern __shared__ __align__(128) char smem[];
    const uint32_t sb = smem_to_u32(smem);
    const int tid = threadIdx.x, wid = tid >> 5, lid = tid & 31;
    const int qt = gridDim.x - 1 - blockIdx.x;   // heavy tiles first
    const int h = blockIdx.y, b = blockIdx.z;
    const int g = h / GROUPSZ;
    const int tg = lid & 3, gr = lid >> 2;

    const size_t qoff   = ((size_t)(b * HH + h) * TT + (size_t)qt * 128) * 64;
    const size_t kvoff0 = ((size_t)(b * GG + g) * TT) * 64;

    auto kv_load = [&](int buf, int kt) {
        const __nv_bfloat16* srcs[4] = {
            khi + kvoff0 + (size_t)kt * 64 * 64,
            klo + kvoff0 + (size_t)kt * 64 * 64,
            vhi + kvoff0 + (size_t)kt * 64 * 64,
            vlo + kvoff0 + (size_t)kt * 64 * 64 };
        uint32_t bbase = sb + buf * 32768;
#pragma unroll
        for (int i = 0; i < 8; i++) {
            int e = i * 256 + tid;
            int part = e >> 9, rr = (e >> 3) & 63, c = e & 7;
            cp_async16(bbase + part * 8192 + rr * 128 + ((c ^ (rr & 7)) << 4),
                       srcs[part] + (size_t)rr * 64 + c * 8);
        }
        cp_commit();
    };

#pragma unroll
    for (int i = 0; i < 8; i++) {
        int e = i * 256 + tid;
        int part = e >> 10, rr = (e >> 3) & 127, c = e & 7;
        const __nv_bfloat16* s = (part ? qlo : qhi) + qoff;
        cp_async16(sb + part * 16384 + rr * 128 + ((c ^ (rr & 7)) << 4),
                   s + (size_t)rr * 64 + c * 8);
    }
    kv_load(1, 0);
    cp_wait<0>();
    __syncthreads();

    uint32_t qhf[4][4], qlf[4][4];
    {
        const int aMat = lid >> 3;
        const int aRow = ((aMat & 1) << 3) + (lid & 7);
        const int aCAdd = aMat >> 1;
#pragma unroll
        for (int kf = 0; kf < 4; kf++) {
            int r = wid * 16 + aRow;
            uint32_t off = r * 128 + (((2 * kf + aCAdd) ^ (r & 7)) << 4);
            ldsm_x4(qhf[kf], sb + off);
            ldsm_x4(qlf[kf], sb + 16384 + off);
        }
    }
    __syncthreads();

    float O[8][4];
#pragma unroll
    for (int nf = 0; nf < 8; nf++)
#pragma unroll
        for (int r = 0; r < 4; r++) O[nf][r] = 0.f;
    float m0 = -INFINITY, m1 = -INFINITY, l0 = 0.f, l1 = 0.f;

    const int nkt = 2 * qt + 2;
    const int bRow = ((lid >> 4) << 3) + (lid & 7);
    const int bCAdd = (lid >> 3) & 1;

    for (int kt = 0; kt < nkt; kt++) {
        if (kt + 1 < nkt) { kv_load(kt & 1, kt + 1); cp_wait<1>(); }
        else              { cp_wait<0>(); }
        __syncthreads();
        const uint32_t kv = sb + ((kt + 1) & 1) * 32768;

        float S[8][4];
#pragma unroll
        for (int nf = 0; nf < 8; nf++)
#pragma unroll
            for (int r = 0; r < 4; r++) S[nf][r] = 0.f;

#pragma unroll
        for (int ks = 0; ks < 4; ks++) {
            uint32_t khf[4][4], klf[4][4];
#pragma unroll
            for (int np = 0; np < 4; np++) {
                int r = np * 16 + bRow;
                uint32_t off = r * 128 + (((2 * ks + bCAdd) ^ (r & 7)) << 4);
                ldsm_x4(khf[np], kv + off);
                ldsm_x4(klf[np], kv + 8192 + off);
            }
#pragma unroll
            for (int np = 0; np < 4; np++)
#pragma unroll
                for (int hf2 = 0; hf2 < 2; hf2++) {
                    int nf = np * 2 + hf2;
                    mma_bf16(S[nf], qhf[ks], khf[np][2 * hf2], khf[np][2 * hf2 + 1]);
                    mma_bf16(S[nf], qlf[ks], khf[np][2 * hf2], khf[np][2 * hf2 + 1]);
                    mma_bf16(S[nf], qhf[ks], klf[np][2 * hf2], klf[np][2 * hf2 + 1]);
                }
        }

        const int row0 = qt * 128 + wid * 16 + gr;
        if (kt * 64 + 63 > row0) {
#pragma unroll
            for (int nf = 0; nf < 8; nf++) {
                int colb = kt * 64 + 8 * nf + 2 * tg;
                if (colb     > row0)     S[nf][0] = -INFINITY;
                if (colb + 1 > row0)     S[nf][1] = -INFINITY;
                if (colb     > row0 + 8) S[nf][2] = -INFINITY;
                if (colb + 1 > row0 + 8) S[nf][3] = -INFINITY;
            }
        }

        float mt0 = m0, mt1 = m1;
#pragma unroll
        for (int nf = 0; nf < 8; nf++) {
            mt0 = fmaxf(mt0, fmaxf(S[nf][0], S[nf][1]));
            mt1 = fmaxf(mt1, fmaxf(S[nf][2], S[nf][3]));
        }
        mt0 = fmaxf(mt0, __shfl_xor_sync(0xffffffffu, mt0, 1));
        mt0 = fmaxf(mt0, __shfl_xor_sync(0xffffffffu, mt0, 2));
        mt1 = fmaxf(mt1, __shfl_xor_sync(0xffffffffu, mt1, 1));
        mt1 = fmaxf(mt1, __shfl_xor_sync(0xffffffffu, mt1, 2));
        float c0 = __expf(m0 - mt0), c1 = __expf(m1 - mt1);
        m0 = mt0; m1 = mt1;
        float ls0 = 0.f, ls1 = 0.f;
#pragma unroll
        for (int nf = 0; nf < 8; nf++) {
            S[nf][0] = __expf(S[nf][0] - mt0); ls0 += S[nf][0];
            S[nf][1] = __expf(S[nf][1] - mt0); ls0 += S[nf][1];
            S[nf][2] = __expf(S[nf][2] - mt1); ls1 += S[nf][2];
            S[nf][3] = __expf(S[nf][3] - mt1); ls1 += S[nf][3];
        }
        l0 = l0 * c0 + ls0;
        l1 = l1 * c1 + ls1;
#pragma unroll
        for (int nf = 0; nf < 8; nf++) {
            O[nf][0] *= c0; O[nf][1] *= c0; O[nf][2] *= c1; O[nf][3] *= c1;
        }

#pragma unroll
        for (int ks = 0; ks < 4; ks++) {
            uint32_t pah[4], pal[4];
            {
                float p[8] = { S[2*ks][0], S[2*ks][1], S[2*ks][2], S[2*ks][3],
                               S[2*ks+1][0], S[2*ks+1][1], S[2*ks+1][2], S[2*ks+1][3] };
                __nv_bfloat16 hh[8], ll[8];
#pragma unroll
                for (int j = 0; j < 8; j++) {
                    hh[j] = __float2bfloat16(p[j]);
                    ll[j] = __float2bfloat16(p[j] - __bfloat162float(hh[j]));
                }
                pah[0] = pkbf2(hh[0], hh[1]); pah[1] = pkbf2(hh[2], hh[3]);
                pah[2] = pkbf2(hh[4], hh[5]); pah[3] = pkbf2(hh[6], hh[7]);
                pal[0] = pkbf2(ll[0], ll[1]); pal[1] = pkbf2(ll[2], ll[3]);
                pal[2] = pkbf2(ll[4], ll[5]); pal[3] = pkbf2(ll[6], ll[7]);
            }
            uint32_t vhf[4][4], vlf[4][4];
            {
                int blk = lid >> 3;
                int r = ks * 16 + ((blk & 1) << 3) + (lid & 7);
#pragma unroll
                for (int np = 0; np < 4; np++) {
                    int chunk = 2 * np + (blk >> 1);
                    uint32_t off = r * 128 + ((chunk ^ (r & 7)) << 4);
                    ldsm_x4_t(vhf[np], kv + 16384 + off);
                    ldsm_x4_t(vlf[np], kv + 24576 + off);
                }
            }
#pragma unroll
            for (int np = 0; np < 4; np++)
#pragma unroll
                for (int hf2 = 0; hf2 < 2; hf2++) {
                    int nf = np * 2 + hf2;
                    mma_bf16(O[nf], pah, vhf[np][2 * hf2], vhf[np][2 * hf2 + 1]);
                    mma_bf16(O[nf], pal, vhf[np][2 * hf2], vhf[np][2 * hf2 + 1]);
                    mma_bf16(O[nf], pah, vlf[np][2 * hf2], vlf[np][2 * hf2 + 1]);
                }
        }
        __syncthreads();
    }

    l0 += __shfl_xor_sync(0xffffffffu, l0, 1);
    l0 += __shfl_xor_sync(0xffffffffu, l0, 2);
    l1 += __shfl_xor_sync(0xffffffffu, l1, 1);
    l1 += __shfl_xor_sync(0xffffffffu, l1, 2);
    const float i0 = 1.f / l0, i1 = 1.f / l1;

    float* stg = (float*)smem;          // [64 hd][132]
#pragma unroll
    for (int nf = 0; nf < 8; nf++) {
        int c = 8 * nf + 2 * tg;
        int q0 = wid * 16 + gr;
        stg[c * 132 + q0]           = O[nf][0] * i0;
        stg[(c + 1) * 132 + q0]     = O[nf][1] * i0;
        stg[c * 132 + q0 + 8]       = O[nf][2] * i1;
        stg[(c + 1) * 132 + q0 + 8] = O[nf][3] * i1;
    }
    __syncthreads();

    const size_t ob = ((size_t)b * DD + (size_t)h * 64) * TT + (size_t)qt * 128;
#pragma unroll
    for (int i = 0; i < 8; i++) {
        int e = i * 256 + tid;
        int c = e >> 5;
        int q4 = e & 31;
        float4 v = *(float4*)&stg[c * 132 + q4 * 4];
        __nv_bfloat16 h0 = __float2bfloat16(v.x), h1 = __float2bfloat16(v.y);
        __nv_bfloat16 h2 = __float2bfloat16(v.z), h3 = __float2bfloat16(v.w);
        uint2 hv, lv;
        hv.x = pkbf2(h0, h1); hv.y = pkbf2(h2, h3);
        lv.x = pkbf2(__float2bfloat16(v.x - __bfloat162float(h0)),
                     __float2bfloat16(v.y - __bfloat162float(h1)));
        lv.y = pkbf2(__float2bfloat16(v.z - __bfloat162float(h2)),
                     __float2bfloat16(v.w - __bfloat162float(h3)));
        size_t dst = ob + (size_t)c * TT + q4 * 4;
        *(uint2*)&chi[dst] = hv;
        *(uint2*)&clo[dst] = lv;
    }
}

// ---------------------------------------------------------------------------
// Launch
// ---------------------------------------------------------------------------
extern "C" void kernel_launch(void* const* d_in, const int* in_sizes, int n_in,
                              void* d_out, int out_size)
{
    const float* x  = (const float*)d_in[0];
    const float* Wq = (const float*)d_in[1];
    const float* Wk = (const float*)d_in[2];
    const float* Wv = (const float*)d_in[3];
    const float* Wo = (const float*)d_in[4];
    float* out = (float*)d_out;

    float *qb, *kb, *vb;
    cudaGetSymbolAddress((void**)&qb, g_q);
    cudaGetSymbolAddress((void**)&kb, g_k);
    cudaGetSymbolAddress((void**)&vb, g_v);
    __nv_bfloat16 *xhi, *xlo, *chi, *clo, *qhi, *qlo, *khi, *klo, *vhi, *vlo;
    __nv_bfloat16 *wqkvh, *wqkvl, *woh, *wol;
    cudaGetSymbolAddress((void**)&xhi, g_xhi);
    cudaGetSymbolAddress((void**)&xlo, g_xlo);
    cudaGetSymbolAddress((void**)&chi, g_chi);
    cudaGetSymbolAddress((void**)&clo, g_clo);
    cudaGetSymbolAddress((void**)&qhi, g_qhi);
    cudaGetSymbolAddress((void**)&qlo, g_qlo);
    cudaGetSymbolAddress((void**)&khi, g_khi);
    cudaGetSymbolAddress((void**)&klo, g_klo);
    cudaGetSymbolAddress((void**)&vhi, g_vhi);
    cudaGetSymbolAddress((void**)&vlo, g_vlo);
    cudaGetSymbolAddress((void**)&wqkvh, g_wqkvhi);
    cudaGetSymbolAddress((void**)&wqkvl, g_wqkvlo);
    cudaGetSymbolAddress((void**)&woh, g_wothi);
    cudaGetSymbolAddress((void**)&wol, g_wotlo);

    const int M = BB * TT;   // 4096

    // split x into bf16 hi/lo
    {
        long n4 = (long)M * DD / 4;
        split_kernel<<<(int)((n4 + 255) / 256), 256>>>(x, xhi, xlo, n4);
    }
    // transpose + split weights; Wq/Wk/Wv concatenated into one [3072][2048] buffer
    {
        dim3 blk(32, 32);
        transpose_split_kernel<<<dim3(DD / 32,  DD / 32), blk>>>(
            Wq, wqkvh, wqkvl, DD, DD);
        transpose_split_kernel<<<dim3(KVD / 32, DD / 32), blk>>>(
            Wk, wqkvh + (size_t)DD * DD, wqkvl + (size_t)DD * DD, DD, KVD);
        transpose_split_kernel<<<dim3(KVD / 32, DD / 32), blk>>>(
            Wv, wqkvh + (size_t)(DD + KVD) * DD, wqkvl + (size_t)(DD + KVD) * DD, DD, KVD);
        transpose_split_kernel<<<dim3(DD / 32,  DD / 32), blk>>>(Wo, woh, wol, DD, DD);
    }

    // fused QKV projection (one launch, head-major scatter epilogue)
    cudaFuncSetAttribute(hmma_gemm_kernel, cudaFuncAttributeMaxDynamicSharedMemorySize,
                         GEMM_SMEM);
    hmma_gemm_kernel<<<dim3(NQKV / 128, M / 128, 1), 256, GEMM_SMEM>>>(
        xhi, xlo, wqkvh, wqkvl, qb, kb, vb, NQKV, DD, 0, 0, 1);

    // merged RoPE/scale/split conversions (one launch)
    {
        long total = QPAIRS + KPAIRS + VPAIRS;
        convert_all_kernel<<<(int)((total + 255) / 256), 256>>>(
            qb, kb, vb, qhi, qlo, khi, klo, vhi, vlo);
    }

    // HMMA flash attention -> chi/clo
    cudaFuncSetAttribute(attn_hmma_kernel, cudaFuncAttributeMaxDynamicSharedMemorySize,
                         ATT_SMEM);
    attn_hmma_kernel<<<dim3(TT / 128, HH, BB), 256, ATT_SMEM>>>(
        qhi, qlo, khi, klo, vhi, vlo, chi, clo);

    // final projection: out[b] = ctxT[b] @ Wo
    hmma_gemm_kernel<<<dim3(DD / 128, DD / 128, BB), 256, GEMM_SMEM>>>(
        chi, clo, woh, wol, out, nullptr, nullptr, DD, DD,
        (long)DD * TT, (long)TT * DD, 0);
}

// round 7
// speedup vs baseline: 3.8761x; 1.0324x over previous
#include <cuda_runtime.h>
#include <cuda_bf16.h>
#include <math.h>
#include <stdint.h>

#define BB 2
#define TT 2048
#define DD 2048
#define HH 32
#define GG 8
#define HDIM 64
#define GROUPSZ 4
#define KVD (GG*HDIM)   // 512
#define NQKV (DD + 2*KVD)   // 3072

// ---------------------------------------------------------------------------
// Scratch (__device__ globals; no allocations allowed)
// ---------------------------------------------------------------------------
__device__ float g_q[(size_t)BB*TT*HH*HDIM];     // [b][h][t][64] fp32 (head-major)
__device__ float g_k[(size_t)BB*TT*GG*HDIM];     // [b][g][t][64]
__device__ float g_v[(size_t)BB*TT*GG*HDIM];     // [b][g][t][64]

__device__ __nv_bfloat16 g_xhi[(size_t)BB*TT*DD];
__device__ __nv_bfloat16 g_xlo[(size_t)BB*TT*DD];
__device__ __nv_bfloat16 g_qhi[(size_t)BB*TT*HH*HDIM];
__device__ __nv_bfloat16 g_qlo[(size_t)BB*TT*HH*HDIM];
__device__ __nv_bfloat16 g_khi[(size_t)BB*TT*GG*HDIM];
__device__ __nv_bfloat16 g_klo[(size_t)BB*TT*GG*HDIM];
__device__ __nv_bfloat16 g_vhi[(size_t)BB*TT*GG*HDIM];
__device__ __nv_bfloat16 g_vlo[(size_t)BB*TT*GG*HDIM];
__device__ __nv_bfloat16 g_chi[(size_t)BB*DD*TT];   // ctx^T hi [b][d][t]
__device__ __nv_bfloat16 g_clo[(size_t)BB*DD*TT];
__device__ __nv_bfloat16 g_wqkvhi[(size_t)NQKV*DD];
__device__ __nv_bfloat16 g_wqkvlo[(size_t)NQKV*DD];
__device__ __nv_bfloat16 g_wothi[(size_t)DD*DD];
__device__ __nv_bfloat16 g_wotlo[(size_t)DD*DD];

// ---------------------------------------------------------------------------
// PTX helpers
// ---------------------------------------------------------------------------
__device__ __forceinline__ uint32_t smem_to_u32(const void* p) {
    uint32_t a;
    asm("{ .reg .u64 tmp; cvta.to.shared.u64 tmp, %1; cvt.u32.u64 %0, tmp; }"
        : "=r"(a) : "l"(p));
    return a;
}
__device__ __forceinline__ void cp_async16(uint32_t dst, const void* src) {
    asm volatile("cp.async.cg.shared.global [%0], [%1], 16;" :: "r"(dst), "l"(src));
}
__device__ __forceinline__ void cp_commit() {
    asm volatile("cp.async.commit_group;" ::: "memory");
}
template <int N> __device__ __forceinline__ void cp_wait() {
    asm volatile("cp.async.wait_group %0;" :: "n"(N) : "memory");
}
__device__ __forceinline__ void ldsm_x4(uint32_t r[4], uint32_t addr) {
    asm volatile("ldmatrix.sync.aligned.m8n8.x4.shared.b16 {%0,%1,%2,%3}, [%4];"
                 : "=r"(r[0]), "=r"(r[1]), "=r"(r[2]), "=r"(r[3]) : "r"(addr));
}
__device__ __forceinline__ void ldsm_x4_t(uint32_t r[4], uint32_t addr) {
    asm volatile("ldmatrix.sync.aligned.m8n8.x4.trans.shared.b16 {%0,%1,%2,%3}, [%4];"
                 : "=r"(r[0]), "=r"(r[1]), "=r"(r[2]), "=r"(r[3]) : "r"(addr));
}
__device__ __forceinline__ void mma_bf16(float c[4], const uint32_t a[4],
                                         const uint32_t b0, const uint32_t b1) {
    asm volatile(
        "mma.sync.aligned.m16n8k16.row.col.f32.bf16.bf16.f32 "
        "{%0,%1,%2,%3}, {%4,%5,%6,%7}, {%8,%9}, {%0,%1,%2,%3};"
        : "+f"(c[0]), "+f"(c[1]), "+f"(c[2]), "+f"(c[3])
        : "r"(a[0]), "r"(a[1]), "r"(a[2]), "r"(a[3]), "r"(b0), "r"(b1));
}
__device__ __forceinline__ uint32_t pkbf2(__nv_bfloat16 a, __nv_bfloat16 b) {
    __nv_bfloat162 t(a, b);
    return *reinterpret_cast<uint32_t*>(&t);
}

// ---------------------------------------------------------------------------
// bf16 hi/lo split of a float array
// ---------------------------------------------------------------------------
__global__ void split_kernel(const float* __restrict__ in,
                             __nv_bfloat16* __restrict__ hi,
                             __nv_bfloat16* __restrict__ lo, long n4)
{
    long i = (long)blockIdx.x * blockDim.x + threadIdx.x;
    if (i >= n4) return;
    float4 v = ((const float4*)in)[i];
    __nv_bfloat16 h0 = __float2bfloat16(v.x);
    __nv_bfloat16 h1 = __float2bfloat16(v.y);
    __nv_bfloat16 h2 = __float2bfloat16(v.z);
    __nv_bfloat16 h3 = __float2bfloat16(v.w);
    ((__nv_bfloat162*)hi)[i * 2 + 0] = __nv_bfloat162(h0, h1);
    ((__nv_bfloat162*)hi)[i * 2 + 1] = __nv_bfloat162(h2, h3);
    ((__nv_bfloat162*)lo)[i * 2 + 0] =
        __nv_bfloat162(__float2bfloat16(v.x - __bfloat162float(h0)),
                       __float2bfloat16(v.y - __bfloat162float(h1)));
    ((__nv_bfloat162*)lo)[i * 2 + 1] =
        __nv_bfloat162(__float2bfloat16(v.z - __bfloat162float(h2)),
                       __float2bfloat16(v.w - __bfloat162float(h3)));
}

// ---------------------------------------------------------------------------
// Merged conversion: RoPE+split q (scaled), RoPE+split k, split v.
// ---------------------------------------------------------------------------
#define QPAIRS ((long)BB*HH*TT*32)
#define KPAIRS ((long)BB*GG*TT*32)
#define VPAIRS ((long)BB*GG*TT*32)

__global__ void convert_all_kernel(
    const float* __restrict__ qsrc, const float* __restrict__ ksrc,
    const float* __restrict__ vsrc,
    __nv_bfloat16* __restrict__ qhi, __nv_bfloat16* __restrict__ qlo,
    __nv_bfloat16* __restrict__ khi, __nv_bfloat16* __restrict__ klo,
    __nv_bfloat16* __restrict__ vhi, __nv_bfloat16* __restrict__ vlo)
{
    long idx = (long)blockIdx.x * blockDim.x + threadIdx.x;
    const float* src;
    __nv_bfloat16 *hi, *lo;
    float scale;
    int doRope;
    if (idx < QPAIRS) {
        src = qsrc; hi = qhi; lo = qlo; scale = 0.125f; doRope = 1;
    } else if (idx < QPAIRS + KPAIRS) {
        idx -= QPAIRS;
        src = ksrc; hi = khi; lo = klo; scale = 1.0f; doRope = 1;
    } else if (idx < QPAIRS + KPAIRS + VPAIRS) {
        idx -= QPAIRS + KPAIRS;
        src = vsrc; hi = vhi; lo = vlo; scale = 1.0f; doRope = 0;
    } else return;

    int d = (int)(idx & 31);
    long u = idx >> 5;
    size_t base = (size_t)u * 64 + d;
    float x1 = src[base];
    float x2 = src[base + 32];
    float y1, y2;
    if (doRope) {
        int t = (int)(u & (TT - 1));
        float e = (float)d * (2.0f / (float)HDIM);
        float inv = 1.0f / powf(10000.0f, e);
        float ang = (float)t * inv;
        float s, c;
        sincosf(ang, &s, &c);
        y1 = (x1 * c - x2 * s) * scale;
        y2 = (x2 * c + x1 * s) * scale;
    } else {
        y1 = x1; y2 = x2;
    }
    __nv_bfloat16 h1 = __float2bfloat16(y1);
    __nv_bfloat16 h2 = __float2bfloat16(y2);
    hi[base]      = h1;
    hi[base + 32] = h2;
    lo[base]      = __float2bfloat16(y1 - __bfloat162float(h1));
    lo[base + 32] = __float2bfloat16(y2 - __bfloat162float(h2));
}

// ---------------------------------------------------------------------------
// Transpose + split: W [K,N] fp32 -> Wt hi/lo [N,K] bf16
// ---------------------------------------------------------------------------
__global__ __launch_bounds__(1024) void transpose_split_kernel(
    const float* __restrict__ W,
    __nv_bfloat16* __restrict__ Thi, __nv_bfloat16* __restrict__ Tlo,
    int K, int N)
{
    __shared__ float tile[32][33];
    int tx = threadIdx.x, ty = threadIdx.y;
    int n0 = blockIdx.x * 32, k0 = blockIdx.y * 32;
    tile[ty][tx] = W[(long)(k0 + ty) * N + n0 + tx];
    __syncthreads();
    float v = tile[tx][ty];
    __nv_bfloat16 h = __float2bfloat16(v);
    __nv_bfloat16 l = __float2bfloat16(v - __bfloat162float(h));
    long oidx = (long)(n0 + ty) * K + k0 + tx;
    Thi[oidx] = h;
    Tlo[oidx] = l;
}

// ---------------------------------------------------------------------------
// HMMA GEMM v2: CTA 128x256, warp tile 64x64 (2x4 warp grid), KC=64.
// C[m][n] = sum_k A[m][k]*B[n][k]; 3-term bf16 hi/lo split.
// mode 0: row-major C.  mode 1: fused-QKV head-major scatter.
// smem: 2 stages x (Ah16K + Al16K + Bh32K + Bl32K) = 192KB.
// ---------------------------------------------------------------------------
#define BM 128
#define BN 256
#define KC 64
#define OFF_AH 0
#define OFF_AL 16384
#define OFF_BH 32768
#define OFF_BL 65536
#define STAGEB 98304
#define GEMM_SMEM (2 * STAGEB)          // 196608

__global__ __launch_bounds__(256, 1)
void hmma_gemm_kernel(const __nv_bfloat16* __restrict__ Ahi,
                      const __nv_bfloat16* __restrict__ Alo,
                      const __nv_bfloat16* __restrict__ Bhi,
                      const __nv_bfloat16* __restrict__ Blo,
                      float* __restrict__ C, float* __restrict__ Ck,
                      float* __restrict__ Cv, int N, int K,
                      long aBatchStride, long cBatchStride, int mode)
{
    extern __shared__ __align__(128) char smem[];
    const uint32_t smem_base = smem_to_u32(smem);
    const int tid = threadIdx.x;
    const int wid = tid >> 5;
    const int lid = tid & 31;

    Ahi += (long)blockIdx.z * aBatchStride;
    Alo += (long)blockIdx.z * aBatchStride;
    C   += (long)blockIdx.z * cBatchStride;

    const int row0 = blockIdx.y * BM;
    const int col0 = blockIdx.x * BN;
    const int Rw = (wid >> 2) * 64;     // 0 or 64
    const int Cw = (wid & 3) * 64;      // 0,64,128,192

    float acc[4][8][4];
#pragma unroll
    for (int i = 0; i < 4; i++)
#pragma unroll
        for (int j = 0; j < 8; j++)
#pragma unroll
            for (int r = 0; r < 4; r++) acc[i][j][r] = 0.f;

    const int aMat  = lid >> 3;
    const int aRow  = ((aMat & 1) << 3) + (lid & 7);
    const int aCAdd = aMat >> 1;
    const int bRow  = ((lid >> 4) << 3) + (lid & 7);
    const int bCAdd = (lid >> 3) & 1;

    const int nch = K / KC;

    auto load_stage = [&](int buf, int k0) {
        uint32_t stage = smem_base + buf * STAGEB;
        // A tiles: 128 rows x 8 chunks each, hi+lo
#pragma unroll
        for (int i = 0; i < 4; i++) {
            int e = i * 256 + tid;
            int r = e >> 3, c = e & 7;
            uint32_t swoff = r * 128 + ((c ^ (r & 7)) << 4);
            const size_t gsrc = (size_t)(row0 + r) * K + k0 + c * 8;
            cp_async16(stage + OFF_AH + swoff, Ahi + gsrc);
            cp_async16(stage + OFF_AL + swoff, Alo + gsrc);
        }
        // B tiles: 256 rows x 8 chunks each, hi+lo
#pragma unroll
        for (int i = 0; i < 8; i++) {
            int e = i * 256 + tid;
            int r = e >> 3, c = e & 7;
            uint32_t swoff = r * 128 + ((c ^ (r & 7)) << 4);
            const size_t gsrc = (size_t)(col0 + r) * K + k0 + c * 8;
            cp_async16(stage + OFF_BH + swoff, Bhi + gsrc);
            cp_async16(stage + OFF_BL + swoff, Blo + gsrc);
        }
        cp_commit();
    };

    load_stage(0, 0);

    for (int ch = 0; ch < nch; ch++) {
        if (ch + 1 < nch) {
            load_stage((ch + 1) & 1, (ch + 1) * KC);
            cp_wait<1>();
        } else {
            cp_wait<0>();
        }
        __syncthreads();

        uint32_t stage = smem_base + (ch & 1) * STAGEB;

#pragma unroll
        for (int ks = 0; ks < 4; ks++) {
            const int c16 = ks * 2;
            uint32_t ah[4][4], al[4][4];
#pragma unroll
            for (int mf = 0; mf < 4; mf++) {
                int r = Rw + mf * 16 + aRow;
                uint32_t off = r * 128 + (((c16 + aCAdd) ^ (r & 7)) << 4);
                ldsm_x4(ah[mf], stage + OFF_AH + off);
                ldsm_x4(al[mf], stage + OFF_AL + off);
            }
#pragma unroll
            for (int np = 0; np < 4; np++) {
                int r = Cw + np * 16 + bRow;
                uint32_t off = r * 128 + (((c16 + bCAdd) ^ (r & 7)) << 4);
                uint32_t bh4[4], bl4[4];
                ldsm_x4(bh4, stage + OFF_BH + off);
                ldsm_x4(bl4, stage + OFF_BL + off);
                const int nf0 = np * 2;
#pragma unroll
                for (int mf = 0; mf < 4; mf++) {
                    mma_bf16(acc[mf][nf0],     ah[mf], bh4[0], bh4[1]);
                    mma_bf16(acc[mf][nf0 + 1], ah[mf], bh4[2], bh4[3]);
                    mma_bf16(acc[mf][nf0],     al[mf], bh4[0], bh4[1]);
                    mma_bf16(acc[mf][nf0 + 1], al[mf], bh4[2], bh4[3]);
                    mma_bf16(acc[mf][nf0],     ah[mf], bl4[0], bl4[1]);
                    mma_bf16(acc[mf][nf0 + 1], ah[mf], bl4[2], bl4[3]);
                }
            }
        }
        __syncthreads();
    }

    // epilogue: stage fp32 through smem (128 x 260 pitch), coalesced stores
    float* stage = (float*)smem;
    const int g  = lid >> 2;
    const int tg = lid & 3;
#pragma unroll
    for (int mf = 0; mf < 4; mf++)
#pragma unroll
        for (int nf = 0; nf < 8; nf++) {
            int row = Rw + mf * 16 + g;
            int col = Cw + nf * 8 + 2 * tg;
            stage[row * 260 + col]           = acc[mf][nf][0];
            stage[row * 260 + col + 1]       = acc[mf][nf][1];
            stage[(row + 8) * 260 + col]     = acc[mf][nf][2];
            stage[(row + 8) * 260 + col + 1] = acc[mf][nf][3];
        }
    __syncthreads();
    // 128 rows x 64 float4 = 8192 slots, 256 threads -> 32 iterations
#pragma unroll
    for (int i = 0; i < 32; i++) {
        int e = i * 256 + tid;
        int r = e >> 6;                 // 0..127
        int c4 = e & 63;                // 0..63
        float4 v = *(float4*)&stage[r * 260 + c4 * 4];
        if (mode == 1) {
            int m = row0 + r;
            int bb = m >> 11;
            int t = m & (TT - 1);
            int col = col0 + c4 * 4;
            float* dstBase;
            int head, nh;
            if (col < DD)            { dstBase = C;  head = col >> 6; nh = HH; }
            else if (col < DD + KVD) { dstBase = Ck; head = (col - DD) >> 6; nh = GG; }
            else                     { dstBase = Cv; head = (col - DD - KVD) >> 6; nh = GG; }
            size_t dst = (((size_t)bb * nh + head) * TT + t) * 64 + (col & 63);
            *(float4*)&dstBase[dst] = v;
        } else {
            *(float4*)&C[(size_t)(row0 + r) * N + col0 + c4 * 4] = v;
        }
    }
}

// ---------------------------------------------------------------------------
// HMMA flash attention (unchanged from R6)
// ---------------------------------------------------------------------------
#define ATT_SMEM 65536

__global__ __launch_bounds__(256, 1) void attn_hmma_kernel(
    const __nv_bfloat16* __restrict__ qhi, const __nv_bfloat16* __restrict__ qlo,
    const __nv_bfloat16* __restrict__ khi, const __nv_bfloat16* __restrict__ klo,
    const __nv_bfloat16* __restrict__ vhi, const __nv_bfloat16* __restrict__ vlo,
    __nv_bfloat16* __restrict__ chi, __nv_bfloat16* __restrict__ clo)
{
    extern __shared__ __align__(128) char smem[];
    const uint32_t sb = smem_to_u32(smem);
    const int tid = threadIdx.x, wid = tid >> 5, lid = tid & 31;
    const int qt = gridDim.x - 1 - blockIdx.x;
    const int h = blockIdx.y, b = blockIdx.z;
    const int g = h / GROUPSZ;
    const int tg = lid & 3, gr = lid >> 2;

    const size_t qoff   = ((size_t)(b * HH + h) * TT + (size_t)qt * 128) * 64;
    const size_t kvoff0 = ((size_t)(b * GG + g) * TT) * 64;

    auto kv_load = [&](int buf, int kt) {
        const __nv_bfloat16* srcs[4] = {
            khi + kvoff0 + (size_t)kt * 64 * 64,
            klo + kvoff0 + (size_t)kt * 64 * 64,
            vhi + kvoff0 + (size_t)kt * 64 * 64,
            vlo + kvoff0 + (size_t)kt * 64 * 64 };
        uint32_t bbase = sb + buf * 32768;
#pragma unroll
        for (int i = 0; i < 8; i++) {
            int e = i * 256 + tid;
            int part = e >> 9, rr = (e >> 3) & 63, c = e & 7;
            cp_async16(bbase + part * 8192 + rr * 128 + ((c ^ (rr & 7)) << 4),
                       srcs[part] + (size_t)rr * 64 + c * 8);
        }
        cp_commit();
    };

#pragma unroll
    for (int i = 0; i < 8; i++) {
        int e = i * 256 + tid;
        int part = e >> 10, rr = (e >> 3) & 127, c = e & 7;
        const __nv_bfloat16* s = (part ? qlo : qhi) + qoff;
        cp_async16(sb + part * 16384 + rr * 128 + ((c ^ (rr & 7)) << 4),
                   s + (size_t)rr * 64 + c * 8);
    }
    kv_load(1, 0);
    cp_wait<0>();
    __syncthreads();

    uint32_t qhf[4][4], qlf[4][4];
    {
        const int aMat = lid >> 3;
        const int aRow = ((aMat & 1) << 3) + (lid & 7);
        const int aCAdd = aMat >> 1;
#pragma unroll
        for (int kf = 0; kf < 4; kf++) {
            int r = wid * 16 + aRow;
            uint32_t off = r * 128 + (((2 * kf + aCAdd) ^ (r & 7)) << 4);
            ldsm_x4(qhf[kf], sb + off);
            ldsm_x4(qlf[kf], sb + 16384 + off);
        }
    }
    __syncthreads();

    float O[8][4];
#pragma unroll
    for (int nf = 0; nf < 8; nf++)
#pragma unroll
        for (int r = 0; r < 4; r++) O[nf][r] = 0.f;
    float m0 = -INFINITY, m1 = -INFINITY, l0 = 0.f, l1 = 0.f;

    const int nkt = 2 * qt + 2;
    const int bRow = ((lid >> 4) << 3) + (lid & 7);
    const int bCAdd = (lid >> 3) & 1;

    for (int kt = 0; kt < nkt; kt++) {
        if (kt + 1 < nkt) { kv_load(kt & 1, kt + 1); cp_wait<1>(); }
        else              { cp_wait<0>(); }
        __syncthreads();
        const uint32_t kv = sb + ((kt + 1) & 1) * 32768;

        float S[8][4];
#pragma unroll
        for (int nf = 0; nf < 8; nf++)
#pragma unroll
            for (int r = 0; r < 4; r++) S[nf][r] = 0.f;

#pragma unroll
        for (int ks = 0; ks < 4; ks++) {
            uint32_t khf[4][4], klf[4][4];
#pragma unroll
            for (int np = 0; np < 4; np++) {
                int r = np * 16 + bRow;
                uint32_t off = r * 128 + (((2 * ks + bCAdd) ^ (r & 7)) << 4);
                ldsm_x4(khf[np], kv + off);
                ldsm_x4(klf[np], kv + 8192 + off);
            }
#pragma unroll
            for (int np = 0; np < 4; np++)
#pragma unroll
                for (int hf2 = 0; hf2 < 2; hf2++) {
                    int nf = np * 2 + hf2;
                    mma_bf16(S[nf], qhf[ks], khf[np][2 * hf2], khf[np][2 * hf2 + 1]);
                    mma_bf16(S[nf], qlf[ks], khf[np][2 * hf2], khf[np][2 * hf2 + 1]);
                    mma_bf16(S[nf], qhf[ks], klf[np][2 * hf2], klf[np][2 * hf2 + 1]);
                }
        }

        const int row0 = qt * 128 + wid * 16 + gr;
        if (kt * 64 + 63 > row0) {
#pragma unroll
            for (int nf = 0; nf < 8; nf++) {
                int colb = kt * 64 + 8 * nf + 2 * tg;
                if (colb     > row0)     S[nf][0] = -INFINITY;
                if (colb + 1 > row0)     S[nf][1] = -INFINITY;
                if (colb     > row0 + 8) S[nf][2] = -INFINITY;
                if (colb + 1 > row0 + 8) S[nf][3] = -INFINITY;
            }
        }

        float mt0 = m0, mt1 = m1;
#pragma unroll
        for (int nf = 0; nf < 8; nf++) {
            mt0 = fmaxf(mt0, fmaxf(S[nf][0], S[nf][1]));
            mt1 = fmaxf(mt1, fmaxf(S[nf][2], S[nf][3]));
        }
        mt0 = fmaxf(mt0, __shfl_xor_sync(0xffffffffu, mt0, 1));
        mt0 = fmaxf(mt0, __shfl_xor_sync(0xffffffffu, mt0, 2));
        mt1 = fmaxf(mt1, __shfl_xor_sync(0xffffffffu, mt1, 1));
        mt1 = fmaxf(mt1, __shfl_xor_sync(0xffffffffu, mt1, 2));
        float c0 = __expf(m0 - mt0), c1 = __expf(m1 - mt1);
        m0 = mt0; m1 = mt1;
        float ls0 = 0.f, ls1 = 0.f;
#pragma unroll
        for (int nf = 0; nf < 8; nf++) {
            S[nf][0] = __expf(S[nf][0] - mt0); ls0 += S[nf][0];
            S[nf][1] = __expf(S[nf][1] - mt0); ls0 += S[nf][1];
            S[nf][2] = __expf(S[nf][2] - mt1); ls1 += S[nf][2];
            S[nf][3] = __expf(S[nf][3] - mt1); ls1 += S[nf][3];
        }
        l0 = l0 * c0 + ls0;
        l1 = l1 * c1 + ls1;
#pragma unroll
        for (int nf = 0; nf < 8; nf++) {
            O[nf][0] *= c0; O[nf][1] *= c0; O[nf][2] *= c1; O[nf][3] *= c1;
        }

#pragma unroll
        for (int ks = 0; ks < 4; ks++) {
            uint32_t pah[4], pal[4];
            {
                float p[8] = { S[2*ks][0], S[2*ks][1], S[2*ks][2], S[2*ks][3],
                               S[2*ks+1][0], S[2*ks+1][1], S[2*ks+1][2], S[2*ks+1][3] };
                __nv_bfloat16 hh[8], ll[8];
#pragma unroll
                for (int j = 0; j < 8; j++) {
                    hh[j] = __float2bfloat16(p[j]);
                    ll[j] = __float2bfloat16(p[j] - __bfloat162float(hh[j]));
                }
                pah[0] = pkbf2(hh[0], hh[1]); pah[1] = pkbf2(hh[2], hh[3]);
                pah[2] = pkbf2(hh[4], hh[5]); pah[3] = pkbf2(hh[6], hh[7]);
                pal[0] = pkbf2(ll[0], ll[1]); pal[1] = pkbf2(ll[2], ll[3]);
                pal[2] = pkbf2(ll[4], ll[5]); pal[3] = pkbf2(ll[6], ll[7]);
            }
            uint32_t vhf[4][4], vlf[4][4];
            {
                int blk = lid >> 3;
                int r = ks * 16 + ((blk & 1) << 3) + (lid & 7);
#pragma unroll
                for (int np = 0; np < 4; np++) {
                    int chunk = 2 * np + (blk >> 1);
                    uint32_t off = r * 128 + ((chunk ^ (r & 7)) << 4);
                    ldsm_x4_t(vhf[np], kv + 16384 + off);
                    ldsm_x4_t(vlf[np], kv + 24576 + off);
                }
            }
#pragma unroll
            for (int np = 0; np < 4; np++)
#pragma unroll
                for (int hf2 = 0; hf2 < 2; hf2++) {
                    int nf = np * 2 + hf2;
                    mma_bf16(O[nf], pah, vhf[np][2 * hf2], vhf[np][2 * hf2 + 1]);
                    mma_bf16(O[nf], pal, vhf[np][2 * hf2], vhf[np][2 * hf2 + 1]);
                    mma_bf16(O[nf], pah, vlf[np][2 * hf2], vlf[np][2 * hf2 + 1]);
                }
        }
        __syncthreads();
    }

    l0 += __shfl_xor_sync(0xffffffffu, l0, 1);
    l0 += __shfl_xor_sync(0xffffffffu, l0, 2);
    l1 += __shfl_xor_sync(0xffffffffu, l1, 1);
    l1 += __shfl_xor_sync(0xffffffffu, l1, 2);
    const float i0 = 1.f / l0, i1 = 1.f / l1;

    float* stg = (float*)smem;
#pragma unroll
    for (int nf = 0; nf < 8; nf++) {
        int c = 8 * nf + 2 * tg;
        int q0 = wid * 16 + gr;
        stg[c * 132 + q0]           = O[nf][0] * i0;
        stg[(c + 1) * 132 + q0]     = O[nf][1] * i0;
        stg[c * 132 + q0 + 8]       = O[nf][2] * i1;
        stg[(c + 1) * 132 + q0 + 8] = O[nf][3] * i1;
    }
    __syncthreads();

    const size_t ob = ((size_t)b * DD + (size_t)h * 64) * TT + (size_t)qt * 128;
#pragma unroll
    for (int i = 0; i < 8; i++) {
        int e = i * 256 + tid;
        int c = e >> 5;
        int q4 = e & 31;
        float4 v = *(float4*)&stg[c * 132 + q4 * 4];
        __nv_bfloat16 h0 = __float2bfloat16(v.x), h1 = __float2bfloat16(v.y);
        __nv_bfloat16 h2 = __float2bfloat16(v.z), h3 = __float2bfloat16(v.w);
        uint2 hv, lv;
        hv.x = pkbf2(h0, h1); hv.y = pkbf2(h2, h3);
        lv.x = pkbf2(__float2bfloat16(v.x - __bfloat162float(h0)),
                     __float2bfloat16(v.y - __bfloat162float(h1)));
        lv.y = pkbf2(__float2bfloat16(v.z - __bfloat162float(h2)),
                     __float2bfloat16(v.w - __bfloat162float(h3)));
        size_t dst = ob + (size_t)c * TT + q4 * 4;
        *(uint2*)&chi[dst] = hv;
        *(uint2*)&clo[dst] = lv;
    }
}

// ---------------------------------------------------------------------------
// Launch
// ---------------------------------------------------------------------------
extern "C" void kernel_launch(void* const* d_in, const int* in_sizes, int n_in,
                              void* d_out, int out_size)
{
    const float* x  = (const float*)d_in[0];
    const float* Wq = (const float*)d_in[1];
    const float* Wk = (const float*)d_in[2];
    const float* Wv = (const float*)d_in[3];
    const float* Wo = (const float*)d_in[4];
    float* out = (float*)d_out;

    float *qb, *kb, *vb;
    cudaGetSymbolAddress((void**)&qb, g_q);
    cudaGetSymbolAddress((void**)&kb, g_k);
    cudaGetSymbolAddress((void**)&vb, g_v);
    __nv_bfloat16 *xhi, *xlo, *chi, *clo, *qhi, *qlo, *khi, *klo, *vhi, *vlo;
    __nv_bfloat16 *wqkvh, *wqkvl, *woh, *wol;
    cudaGetSymbolAddress((void**)&xhi, g_xhi);
    cudaGetSymbolAddress((void**)&xlo, g_xlo);
    cudaGetSymbolAddress((void**)&chi, g_chi);
    cudaGetSymbolAddress((void**)&clo, g_clo);
    cudaGetSymbolAddress((void**)&qhi, g_qhi);
    cudaGetSymbolAddress((void**)&qlo, g_qlo);
    cudaGetSymbolAddress((void**)&khi, g_khi);
    cudaGetSymbolAddress((void**)&klo, g_klo);
    cudaGetSymbolAddress((void**)&vhi, g_vhi);
    cudaGetSymbolAddress((void**)&vlo, g_vlo);
    cudaGetSymbolAddress((void**)&wqkvh, g_wqkvhi);
    cudaGetSymbolAddress((void**)&wqkvl, g_wqkvlo);
    cudaGetSymbolAddress((void**)&woh, g_wothi);
    cudaGetSymbolAddress((void**)&wol, g_wotlo);

    const int M = BB * TT;   // 4096

    {
        long n4 = (long)M * DD / 4;
        split_kernel<<<(int)((n4 + 255) / 256), 256>>>(x, xhi, xlo, n4);
    }
    {
        dim3 blk(32, 32);
        transpose_split_kernel<<<dim3(DD / 32,  DD / 32), blk>>>(
            Wq, wqkvh, wqkvl, DD, DD);
        transpose_split_kernel<<<dim3(KVD / 32, DD / 32), blk>>>(
            Wk, wqkvh + (size_t)DD * DD, wqkvl + (size_t)DD * DD, DD, KVD);
        transpose_split_kernel<<<dim3(KVD / 32, DD / 32), blk>>>(
            Wv, wqkvh + (size_t)(DD + KVD) * DD, wqkvl + (size_t)(DD + KVD) * DD, DD, KVD);
        transpose_split_kernel<<<dim3(DD / 32,  DD / 32), blk>>>(Wo, woh, wol, DD, DD);
    }

    // fused QKV projection
    cudaFuncSetAttribute(hmma_gemm_kernel, cudaFuncAttributeMaxDynamicSharedMemorySize,
                         GEMM_SMEM);
    hmma_gemm_kernel<<<dim3(NQKV / BN, M / BM, 1), 256, GEMM_SMEM>>>(
        xhi, xlo, wqkvh, wqkvl, qb, kb, vb, NQKV, DD, 0, 0, 1);

    {
        long total = QPAIRS + KPAIRS + VPAIRS;
        convert_all_kernel<<<(int)((total + 255) / 256), 256>>>(
            qb, kb, vb, qhi, qlo, khi, klo, vhi, vlo);
    }

    cudaFuncSetAttribute(attn_hmma_kernel, cudaFuncAttributeMaxDynamicSharedMemorySize,
                         ATT_SMEM);
    attn_hmma_kernel<<<dim3(TT / 128, HH, BB), 256, ATT_SMEM>>>(
        qhi, qlo, khi, klo, vhi, vlo, chi, clo);

    hmma_gemm_kernel<<<dim3(DD / BN, DD / BM, BB), 256, GEMM_SMEM>>>(
        chi, clo, woh, wol, out, nullptr, nullptr, DD, DD,
        (long)DD * TT, (long)TT * DD, 0);
}

// round 8
// speedup vs baseline: 5.2468x; 1.3536x over previous
#include <cuda_runtime.h>
#include <cuda_fp16.h>
#include <math.h>
#include <stdint.h>

#define BB 2
#define TT 2048
#define DD 2048
#define HH 32
#define GG 8
#define HDIM 64
#define GROUPSZ 4
#define KVD (GG*HDIM)   // 512
#define NQKV (DD + 2*KVD)   // 3072

// ---------------------------------------------------------------------------
// Scratch (__device__ globals; no allocations allowed)
// ---------------------------------------------------------------------------
__device__ float g_q[(size_t)BB*TT*HH*HDIM];     // [b][h][t][64] fp32 head-major
__device__ float g_k[(size_t)BB*TT*GG*HDIM];
__device__ float g_v[(size_t)BB*TT*GG*HDIM];

__device__ __half g_xhi[(size_t)BB*TT*DD];
__device__ __half g_xlo[(size_t)BB*TT*DD];
__device__ __half g_qhi[(size_t)BB*TT*HH*HDIM];
__device__ __half g_qlo[(size_t)BB*TT*HH*HDIM];
__device__ __half g_khi[(size_t)BB*TT*GG*HDIM];   // hi only
__device__ __half g_vhi[(size_t)BB*TT*GG*HDIM];   // hi only
__device__ __half g_chi[(size_t)BB*DD*TT];        // ctx^T hi [b][d][t]
__device__ __half g_clo[(size_t)BB*DD*TT];
__device__ __half g_wqkvhi[(size_t)NQKV*DD];      // hi only
__device__ __half g_wothi[(size_t)DD*DD];         // hi only

// ---------------------------------------------------------------------------
// PTX helpers
// ---------------------------------------------------------------------------
__device__ __forceinline__ uint32_t smem_to_u32(const void* p) {
    uint32_t a;
    asm("{ .reg .u64 tmp; cvta.to.shared.u64 tmp, %1; cvt.u32.u64 %0, tmp; }"
        : "=r"(a) : "l"(p));
    return a;
}
__device__ __forceinline__ void cp_async16(uint32_t dst, const void* src) {
    asm volatile("cp.async.cg.shared.global [%0], [%1], 16;" :: "r"(dst), "l"(src));
}
__device__ __forceinline__ void cp_commit() {
    asm volatile("cp.async.commit_group;" ::: "memory");
}
template <int N> __device__ __forceinline__ void cp_wait() {
    asm volatile("cp.async.wait_group %0;" :: "n"(N) : "memory");
}
__device__ __forceinline__ void ldsm_x4(uint32_t r[4], uint32_t addr) {
    asm volatile("ldmatrix.sync.aligned.m8n8.x4.shared.b16 {%0,%1,%2,%3}, [%4];"
                 : "=r"(r[0]), "=r"(r[1]), "=r"(r[2]), "=r"(r[3]) : "r"(addr));
}
__device__ __forceinline__ void ldsm_x4_t(uint32_t r[4], uint32_t addr) {
    asm volatile("ldmatrix.sync.aligned.m8n8.x4.trans.shared.b16 {%0,%1,%2,%3}, [%4];"
                 : "=r"(r[0]), "=r"(r[1]), "=r"(r[2]), "=r"(r[3]) : "r"(addr));
}
__device__ __forceinline__ void mma_f16(float c[4], const uint32_t a[4],
                                        const uint32_t b0, const uint32_t b1) {
    asm volatile(
        "mma.sync.aligned.m16n8k16.row.col.f32.f16.f16.f32 "
        "{%0,%1,%2,%3}, {%4,%5,%6,%7}, {%8,%9}, {%0,%1,%2,%3};"
        : "+f"(c[0]), "+f"(c[1]), "+f"(c[2]), "+f"(c[3])
        : "r"(a[0]), "r"(a[1]), "r"(a[2]), "r"(a[3]), "r"(b0), "r"(b1));
}
__device__ __forceinline__ uint32_t pkh2(__half a, __half b) {
    __half2 t(a, b);
    return *reinterpret_cast<uint32_t*>(&t);
}

// ---------------------------------------------------------------------------
// fp16 hi/lo split of a float array
// ---------------------------------------------------------------------------
__global__ void split_kernel(const float* __restrict__ in,
                             __half* __restrict__ hi,
                             __half* __restrict__ lo, long n4)
{
    long i = (long)blockIdx.x * blockDim.x + threadIdx.x;
    if (i >= n4) return;
    float4 v = ((const float4*)in)[i];
    __half h0 = __float2half(v.x);
    __half h1 = __float2half(v.y);
    __half h2 = __float2half(v.z);
    __half h3 = __float2half(v.w);
    ((__half2*)hi)[i * 2 + 0] = __half2(h0, h1);
    ((__half2*)hi)[i * 2 + 1] = __half2(h2, h3);
    ((__half2*)lo)[i * 2 + 0] = __half2(__float2half(v.x - __half2float(h0)),
                                        __float2half(v.y - __half2float(h1)));
    ((__half2*)lo)[i * 2 + 1] = __half2(__float2half(v.z - __half2float(h2)),
                                        __float2half(v.w - __half2float(h3)));
}

// ---------------------------------------------------------------------------
// Merged conversion: q -> rope+scale, split hi/lo; k -> rope, hi; v -> hi.
// ---------------------------------------------------------------------------
#define QPAIRS ((long)BB*HH*TT*32)
#define KPAIRS ((long)BB*GG*TT*32)
#define VPAIRS ((long)BB*GG*TT*32)

__global__ void convert_all_kernel(
    const float* __restrict__ qsrc, const float* __restrict__ ksrc,
    const float* __restrict__ vsrc,
    __half* __restrict__ qhi, __half* __restrict__ qlo,
    __half* __restrict__ khi, __half* __restrict__ vhi)
{
    long idx = (long)blockIdx.x * blockDim.x + threadIdx.x;
    const float* src;
    __half *hi, *lo;
    float scale;
    int doRope;
    if (idx < QPAIRS) {
        src = qsrc; hi = qhi; lo = qlo; scale = 0.125f; doRope = 1;
    } else if (idx < QPAIRS + KPAIRS) {
        idx -= QPAIRS;
        src = ksrc; hi = khi; lo = nullptr; scale = 1.0f; doRope = 1;
    } else if (idx < QPAIRS + KPAIRS + VPAIRS) {
        idx -= QPAIRS + KPAIRS;
        src = vsrc; hi = vhi; lo = nullptr; scale = 1.0f; doRope = 0;
    } else return;

    int d = (int)(idx & 31);
    long u = idx >> 5;
    size_t base = (size_t)u * 64 + d;
    float x1 = src[base];
    float x2 = src[base + 32];
    float y1, y2;
    if (doRope) {
        int t = (int)(u & (TT - 1));
        float e = (float)d * (2.0f / (float)HDIM);
        float inv = 1.0f / powf(10000.0f, e);
        float ang = (float)t * inv;
        float s, c;
        sincosf(ang, &s, &c);
        y1 = (x1 * c - x2 * s) * scale;
        y2 = (x2 * c + x1 * s) * scale;
    } else {
        y1 = x1; y2 = x2;
    }
    __half h1 = __float2half(y1);
    __half h2 = __float2half(y2);
    hi[base]      = h1;
    hi[base + 32] = h2;
    if (lo) {
        lo[base]      = __float2half(y1 - __half2float(h1));
        lo[base + 32] = __float2half(y2 - __half2float(h2));
    }
}

// ---------------------------------------------------------------------------
// Transpose (+optional lo): W [K,N] fp32 -> Wt hi [N,K] fp16
// ---------------------------------------------------------------------------
__global__ __launch_bounds__(1024) void transpose_split_kernel(
    const float* __restrict__ W,
    __half* __restrict__ Thi, __half* __restrict__ Tlo,
    int K, int N)
{
    __shared__ float tile[32][33];
    int tx = threadIdx.x, ty = threadIdx.y;
    int n0 = blockIdx.x * 32, k0 = blockIdx.y * 32;
    tile[ty][tx] = W[(long)(k0 + ty) * N + n0 + tx];
    __syncthreads();
    float v = tile[tx][ty];
    __half h = __float2half(v);
    long oidx = (long)(n0 + ty) * K + k0 + tx;
    Thi[oidx] = h;
    if (Tlo) Tlo[oidx] = __float2half(v - __half2float(h));
}

// ---------------------------------------------------------------------------
// HMMA GEMM: CTA 128x256, warp 64x64, KC=64. fp16 2-term:
// C = (Ah+Al)*Bh with fp32 accumulate. mode 1: fused-QKV head-major scatter.
// smem: 2 stages x (Ah16K + Al16K + Bh32K) = 128KB; epilogue needs 130.1KB.
// ---------------------------------------------------------------------------
#define BM 128
#define BN 256
#define KC 64
#define OFF_AH 0
#define OFF_AL 16384
#define OFF_BH 32768
#define STAGEB 65536
#define GEMM_SMEM 135168

__global__ __launch_bounds__(256, 1)
void hmma_gemm_kernel(const __half* __restrict__ Ahi,
                      const __half* __restrict__ Alo,
                      const __half* __restrict__ Bhi,
                      float* __restrict__ C, float* __restrict__ Ck,
                      float* __restrict__ Cv, int N, int K,
                      long aBatchStride, long cBatchStride, int mode)
{
    extern __shared__ __align__(128) char smem[];
    const uint32_t smem_base = smem_to_u32(smem);
    const int tid = threadIdx.x;
    const int wid = tid >> 5;
    const int lid = tid & 31;

    Ahi += (long)blockIdx.z * aBatchStride;
    Alo += (long)blockIdx.z * aBatchStride;
    C   += (long)blockIdx.z * cBatchStride;

    const int row0 = blockIdx.y * BM;
    const int col0 = blockIdx.x * BN;
    const int Rw = (wid >> 2) * 64;
    const int Cw = (wid & 3) * 64;

    float acc[4][8][4];
#pragma unroll
    for (int i = 0; i < 4; i++)
#pragma unroll
        for (int j = 0; j < 8; j++)
#pragma unroll
            for (int r = 0; r < 4; r++) acc[i][j][r] = 0.f;

    const int aMat  = lid >> 3;
    const int aRow  = ((aMat & 1) << 3) + (lid & 7);
    const int aCAdd = aMat >> 1;
    const int bRow  = ((lid >> 4) << 3) + (lid & 7);
    const int bCAdd = (lid >> 3) & 1;

    const int nch = K / KC;

    auto load_stage = [&](int buf, int k0) {
        uint32_t stage = smem_base + buf * STAGEB;
#pragma unroll
        for (int i = 0; i < 4; i++) {
            int e = i * 256 + tid;
            int r = e >> 3, c = e & 7;
            uint32_t swoff = r * 128 + ((c ^ (r & 7)) << 4);
            const size_t gsrc = (size_t)(row0 + r) * K + k0 + c * 8;
            cp_async16(stage + OFF_AH + swoff, Ahi + gsrc);
            cp_async16(stage + OFF_AL + swoff, Alo + gsrc);
        }
#pragma unroll
        for (int i = 0; i < 8; i++) {
            int e = i * 256 + tid;
            int r = e >> 3, c = e & 7;
            uint32_t swoff = r * 128 + ((c ^ (r & 7)) << 4);
            cp_async16(stage + OFF_BH + swoff, Bhi + (size_t)(col0 + r) * K + k0 + c * 8);
        }
        cp_commit();
    };

    load_stage(0, 0);

    for (int ch = 0; ch < nch; ch++) {
        if (ch + 1 < nch) {
            load_stage((ch + 1) & 1, (ch + 1) * KC);
            cp_wait<1>();
        } else {
            cp_wait<0>();
        }
        __syncthreads();

        uint32_t stage = smem_base + (ch & 1) * STAGEB;

#pragma unroll
        for (int ks = 0; ks < 4; ks++) {
            const int c16 = ks * 2;
            uint32_t ah[4][4], al[4][4];
#pragma unroll
            for (int mf = 0; mf < 4; mf++) {
                int r = Rw + mf * 16 + aRow;
                uint32_t off = r * 128 + (((c16 + aCAdd) ^ (r & 7)) << 4);
                ldsm_x4(ah[mf], stage + OFF_AH + off);
                ldsm_x4(al[mf], stage + OFF_AL + off);
            }
#pragma unroll
            for (int np = 0; np < 4; np++) {
                int r = Cw + np * 16 + bRow;
                uint32_t off = r * 128 + (((c16 + bCAdd) ^ (r & 7)) << 4);
                uint32_t bh4[4];
                ldsm_x4(bh4, stage + OFF_BH + off);
                const int nf0 = np * 2;
#pragma unroll
                for (int mf = 0; mf < 4; mf++) {
                    mma_f16(acc[mf][nf0],     ah[mf], bh4[0], bh4[1]);
                    mma_f16(acc[mf][nf0 + 1], ah[mf], bh4[2], bh4[3]);
                }
#pragma unroll
                for (int mf = 0; mf < 4; mf++) {
                    mma_f16(acc[mf][nf0],     al[mf], bh4[0], bh4[1]);
                    mma_f16(acc[mf][nf0 + 1], al[mf], bh4[2], bh4[3]);
                }
            }
        }
        __syncthreads();
    }

    // epilogue: stage fp32 through smem (pitch 260), coalesced stores
    float* stage = (float*)smem;
    const int g  = lid >> 2;
    const int tg = lid & 3;
#pragma unroll
    for (int mf = 0; mf < 4; mf++)
#pragma unroll
        for (int nf = 0; nf < 8; nf++) {
            int row = Rw + mf * 16 + g;
            int col = Cw + nf * 8 + 2 * tg;
            stage[row * 260 + col]           = acc[mf][nf][0];
            stage[row * 260 + col + 1]       = acc[mf][nf][1];
            stage[(row + 8) * 260 + col]     = acc[mf][nf][2];
            stage[(row + 8) * 260 + col + 1] = acc[mf][nf][3];
        }
    __syncthreads();
#pragma unroll
    for (int i = 0; i < 32; i++) {
        int e = i * 256 + tid;
        int r = e >> 6;
        int c4 = e & 63;
        float4 v = *(float4*)&stage[r * 260 + c4 * 4];
        if (mode == 1) {
            int m = row0 + r;
            int bb = m >> 11;
            int t = m & (TT - 1);
            int col = col0 + c4 * 4;
            float* dstBase;
            int head, nh;
            if (col < DD)            { dstBase = C;  head = col >> 6; nh = HH; }
            else if (col < DD + KVD) { dstBase = Ck; head = (col - DD) >> 6; nh = GG; }
            else                     { dstBase = Cv; head = (col - DD - KVD) >> 6; nh = GG; }
            size_t dst = (((size_t)bb * nh + head) * TT + t) * 64 + (col & 63);
            *(float4*)&dstBase[dst] = v;
        } else {
            *(float4*)&C[(size_t)(row0 + r) * N + col0 + c4 * 4] = v;
        }
    }
}

// ---------------------------------------------------------------------------
// HMMA flash attention (causal, GQA), fp16 2-term.
// Q hi/lo in regs; Kh/Vh tiles (16KB) double-buffered.
// S = Qh Kh + Ql Kh;  O += Ph Vh + Pl Vh  (P split in regs).
// ---------------------------------------------------------------------------
#define ATT_SMEM 65536   // Q 32K | kv buf0 16K | kv buf1 16K

__global__ __launch_bounds__(256, 1) void attn_hmma_kernel(
    const __half* __restrict__ qhi, const __half* __restrict__ qlo,
    const __half* __restrict__ khi, const __half* __restrict__ vhi,
    __half* __restrict__ chi, __half* __restrict__ clo)
{
    extern __shared__ __align__(128) char smem[];
    const uint32_t sb = smem_to_u32(smem);
    const int tid = threadIdx.x, wid = tid >> 5, lid = tid & 31;
    const int qt = gridDim.x - 1 - blockIdx.x;
    const int h = blockIdx.y, b = blockIdx.z;
    const int g = h / GROUPSZ;
    const int tg = lid & 3, gr = lid >> 2;

    const size_t qoff   = ((size_t)(b * HH + h) * TT + (size_t)qt * 128) * 64;
    const size_t kvoff0 = ((size_t)(b * GG + g) * TT) * 64;

    auto kv_load = [&](int buf, int kt) {
        const __half* srcs[2] = {
            khi + kvoff0 + (size_t)kt * 64 * 64,
            vhi + kvoff0 + (size_t)kt * 64 * 64 };
        uint32_t bbase = sb + 32768 + buf * 16384;
#pragma unroll
        for (int i = 0; i < 4; i++) {
            int e = i * 256 + tid;
            int part = e >> 9, rr = (e >> 3) & 63, c = e & 7;
            cp_async16(bbase + part * 8192 + rr * 128 + ((c ^ (rr & 7)) << 4),
                       srcs[part] + (size_t)rr * 64 + c * 8);
        }
        cp_commit();
    };

#pragma unroll
    for (int i = 0; i < 8; i++) {
        int e = i * 256 + tid;
        int part = e >> 10, rr = (e >> 3) & 127, c = e & 7;
        const __half* s = (part ? qlo : qhi) + qoff;
        cp_async16(sb + part * 16384 + rr * 128 + ((c ^ (rr & 7)) << 4),
                   s + (size_t)rr * 64 + c * 8);
    }
    kv_load(1, 0);
    cp_wait<0>();
    __syncthreads();

    uint32_t qhf[4][4], qlf[4][4];
    {
        const int aMat = lid >> 3;
        const int aRow = ((aMat & 1) << 3) + (lid & 7);
        const int aCAdd = aMat >> 1;
#pragma unroll
        for (int kf = 0; kf < 4; kf++) {
            int r = wid * 16 + aRow;
            uint32_t off = r * 128 + (((2 * kf + aCAdd) ^ (r & 7)) << 4);
            ldsm_x4(qhf[kf], sb + off);
            ldsm_x4(qlf[kf], sb + 16384 + off);
        }
    }
    __syncthreads();

    float O[8][4];
#pragma unroll
    for (int nf = 0; nf < 8; nf++)
#pragma unroll
        for (int r = 0; r < 4; r++) O[nf][r] = 0.f;
    float m0 = -INFINITY, m1 = -INFINITY, l0 = 0.f, l1 = 0.f;

    const int nkt = 2 * qt + 2;
    const int bRow = ((lid >> 4) << 3) + (lid & 7);
    const int bCAdd = (lid >> 3) & 1;

    for (int kt = 0; kt < nkt; kt++) {
        if (kt + 1 < nkt) { kv_load(kt & 1, kt + 1); cp_wait<1>(); }
        else              { cp_wait<0>(); }
        __syncthreads();
        const uint32_t kv = sb + 32768 + ((kt + 1) & 1) * 16384;

        float S[8][4];
#pragma unroll
        for (int nf = 0; nf < 8; nf++)
#pragma unroll
            for (int r = 0; r < 4; r++) S[nf][r] = 0.f;

#pragma unroll
        for (int ks = 0; ks < 4; ks++) {
            uint32_t khf[4][4];
#pragma unroll
            for (int np = 0; np < 4; np++) {
                int r = np * 16 + bRow;
                uint32_t off = r * 128 + (((2 * ks + bCAdd) ^ (r & 7)) << 4);
                ldsm_x4(khf[np], kv + off);
            }
#pragma unroll
            for (int np = 0; np < 4; np++) {
                mma_f16(S[np * 2],     qhf[ks], khf[np][0], khf[np][1]);
                mma_f16(S[np * 2 + 1], qhf[ks], khf[np][2], khf[np][3]);
            }
#pragma unroll
            for (int np = 0; np < 4; np++) {
                mma_f16(S[np * 2],     qlf[ks], khf[np][0], khf[np][1]);
                mma_f16(S[np * 2 + 1], qlf[ks], khf[np][2], khf[np][3]);
            }
        }

        const int row0 = qt * 128 + wid * 16 + gr;
        if (kt * 64 + 63 > row0) {
#pragma unroll
            for (int nf = 0; nf < 8; nf++) {
                int colb = kt * 64 + 8 * nf + 2 * tg;
                if (colb     > row0)     S[nf][0] = -INFINITY;
                if (colb + 1 > row0)     S[nf][1] = -INFINITY;
                if (colb     > row0 + 8) S[nf][2] = -INFINITY;
                if (colb + 1 > row0 + 8) S[nf][3] = -INFINITY;
            }
        }

        float mt0 = m0, mt1 = m1;
#pragma unroll
        for (int nf = 0; nf < 8; nf++) {
            mt0 = fmaxf(mt0, fmaxf(S[nf][0], S[nf][1]));
            mt1 = fmaxf(mt1, fmaxf(S[nf][2], S[nf][3]));
        }
        mt0 = fmaxf(mt0, __shfl_xor_sync(0xffffffffu, mt0, 1));
        mt0 = fmaxf(mt0, __shfl_xor_sync(0xffffffffu, mt0, 2));
        mt1 = fmaxf(mt1, __shfl_xor_sync(0xffffffffu, mt1, 1));
        mt1 = fmaxf(mt1, __shfl_xor_sync(0xffffffffu, mt1, 2));
        float c0 = __expf(m0 - mt0), c1 = __expf(m1 - mt1);
        m0 = mt0; m1 = mt1;
        float ls0 = 0.f, ls1 = 0.f;
#pragma unroll
        for (int nf = 0; nf < 8; nf++) {
            S[nf][0] = __expf(S[nf][0] - mt0); ls0 += S[nf][0];
            S[nf][1] = __expf(S[nf][1] - mt0); ls0 += S[nf][1];
            S[nf][2] = __expf(S[nf][2] - mt1); ls1 += S[nf][2];
            S[nf][3] = __expf(S[nf][3] - mt1); ls1 += S[nf][3];
        }
        l0 = l0 * c0 + ls0;
        l1 = l1 * c1 + ls1;
#pragma unroll
        for (int nf = 0; nf < 8; nf++) {
            O[nf][0] *= c0; O[nf][1] *= c0; O[nf][2] *= c1; O[nf][3] *= c1;
        }

#pragma unroll
        for (int ks = 0; ks < 4; ks++) {
            uint32_t pah[4], pal[4];
            {
                float p[8] = { S[2*ks][0], S[2*ks][1], S[2*ks][2], S[2*ks][3],
                               S[2*ks+1][0], S[2*ks+1][1], S[2*ks+1][2], S[2*ks+1][3] };
                __half hh[8], ll[8];
#pragma unroll
                for (int j = 0; j < 8; j++) {
                    hh[j] = __float2half(p[j]);
                    ll[j] = __float2half(p[j] - __half2float(hh[j]));
                }
                pah[0] = pkh2(hh[0], hh[1]); pah[1] = pkh2(hh[2], hh[3]);
                pah[2] = pkh2(hh[4], hh[5]); pah[3] = pkh2(hh[6], hh[7]);
                pal[0] = pkh2(ll[0], ll[1]); pal[1] = pkh2(ll[2], ll[3]);
                pal[2] = pkh2(ll[4], ll[5]); pal[3] = pkh2(ll[6], ll[7]);
            }
            uint32_t vhf[4][4];
            {
                int blk = lid >> 3;
                int r = ks * 16 + ((blk & 1) << 3) + (lid & 7);
#pragma unroll
                for (int np = 0; np < 4; np++) {
                    int chunk = 2 * np + (blk >> 1);
                    uint32_t off = r * 128 + ((chunk ^ (r & 7)) << 4);
                    ldsm_x4_t(vhf[np], kv + 8192 + off);
                }
            }
#pragma unroll
            for (int np = 0; np < 4; np++) {
                mma_f16(O[np * 2],     pah, vhf[np][0], vhf[np][1]);
                mma_f16(O[np * 2 + 1], pah, vhf[np][2], vhf[np][3]);
            }
#pragma unroll
            for (int np = 0; np < 4; np++) {
                mma_f16(O[np * 2],     pal, vhf[np][0], vhf[np][1]);
                mma_f16(O[np * 2 + 1], pal, vhf[np][2], vhf[np][3]);
            }
        }
        __syncthreads();
    }

    l0 += __shfl_xor_sync(0xffffffffu, l0, 1);
    l0 += __shfl_xor_sync(0xffffffffu, l0, 2);
    l1 += __shfl_xor_sync(0xffffffffu, l1, 1);
    l1 += __shfl_xor_sync(0xffffffffu, l1, 2);
    const float i0 = 1.f / l0, i1 = 1.f / l1;

    float* stg = (float*)smem;
#pragma unroll
    for (int nf = 0; nf < 8; nf++) {
        int c = 8 * nf + 2 * tg;
        int q0 = wid * 16 + gr;
        stg[c * 132 + q0]           = O[nf][0] * i0;
        stg[(c + 1) * 132 + q0]     = O[nf][1] * i0;
        stg[c * 132 + q0 + 8]       = O[nf][2] * i1;
        stg[(c + 1) * 132 + q0 + 8] = O[nf][3] * i1;
    }
    __syncthreads();

    const size_t ob = ((size_t)b * DD + (size_t)h * 64) * TT + (size_t)qt * 128;
#pragma unroll
    for (int i = 0; i < 8; i++) {
        int e = i * 256 + tid;
        int c = e >> 5;
        int q4 = e & 31;
        float4 v = *(float4*)&stg[c * 132 + q4 * 4];
        __half h0 = __float2half(v.x), h1 = __float2half(v.y);
        __half h2 = __float2half(v.z), h3 = __float2half(v.w);
        uint2 hv, lv;
        hv.x = pkh2(h0, h1); hv.y = pkh2(h2, h3);
        lv.x = pkh2(__float2half(v.x - __half2float(h0)),
                    __float2half(v.y - __half2float(h1)));
        lv.y = pkh2(__float2half(v.z - __half2float(h2)),
                    __float2half(v.w - __half2float(h3)));
        size_t dst = ob + (size_t)c * TT + q4 * 4;
        *(uint2*)&chi[dst] = hv;
        *(uint2*)&clo[dst] = lv;
    }
}

// ---------------------------------------------------------------------------
// Launch
// ---------------------------------------------------------------------------
extern "C" void kernel_launch(void* const* d_in, const int* in_sizes, int n_in,
                              void* d_out, int out_size)
{
    const float* x  = (const float*)d_in[0];
    const float* Wq = (const float*)d_in[1];
    const float* Wk = (const float*)d_in[2];
    const float* Wv = (const float*)d_in[3];
    const float* Wo = (const float*)d_in[4];
    float* out = (float*)d_out;

    float *qb, *kb, *vb;
    cudaGetSymbolAddress((void**)&qb, g_q);
    cudaGetSymbolAddress((void**)&kb, g_k);
    cudaGetSymbolAddress((void**)&vb, g_v);
    __half *xhi, *xlo, *chi, *clo, *qhi, *qlo, *khi, *vhi, *wqkvh, *woh;
    cudaGetSymbolAddress((void**)&xhi, g_xhi);
    cudaGetSymbolAddress((void**)&xlo, g_xlo);
    cudaGetSymbolAddress((void**)&chi, g_chi);
    cudaGetSymbolAddress((void**)&clo, g_clo);
    cudaGetSymbolAddress((void**)&qhi, g_qhi);
    cudaGetSymbolAddress((void**)&qlo, g_qlo);
    cudaGetSymbolAddress((void**)&khi, g_khi);
    cudaGetSymbolAddress((void**)&vhi, g_vhi);
    cudaGetSymbolAddress((void**)&wqkvh, g_wqkvhi);
    cudaGetSymbolAddress((void**)&woh, g_wothi);

    const int M = BB * TT;   // 4096

    {
        long n4 = (long)M * DD / 4;
        split_kernel<<<(int)((n4 + 255) / 256), 256>>>(x, xhi, xlo, n4);
    }
    {
        dim3 blk(32, 32);
        transpose_split_kernel<<<dim3(DD / 32,  DD / 32), blk>>>(
            Wq, wqkvh, nullptr, DD, DD);
        transpose_split_kernel<<<dim3(KVD / 32, DD / 32), blk>>>(
            Wk, wqkvh + (size_t)DD * DD, nullptr, DD, KVD);
        transpose_split_kernel<<<dim3(KVD / 32, DD / 32), blk>>>(
            Wv, wqkvh + (size_t)(DD + KVD) * DD, nullptr, DD, KVD);
        transpose_split_kernel<<<dim3(DD / 32,  DD / 32), blk>>>(Wo, woh, nullptr, DD, DD);
    }

    // fused QKV projection
    cudaFuncSetAttribute(hmma_gemm_kernel, cudaFuncAttributeMaxDynamicSharedMemorySize,
                         GEMM_SMEM);
    hmma_gemm_kernel<<<dim3(NQKV / BN, M / BM, 1), 256, GEMM_SMEM>>>(
        xhi, xlo, wqkvh, qb, kb, vb, NQKV, DD, 0, 0, 1);

    {
        long total = QPAIRS + KPAIRS + VPAIRS;
        convert_all_kernel<<<(int)((total + 255) / 256), 256>>>(
            qb, kb, vb, qhi, qlo, khi, vhi);
    }

    cudaFuncSetAttribute(attn_hmma_kernel, cudaFuncAttributeMaxDynamicSharedMemorySize,
                         ATT_SMEM);
    attn_hmma_kernel<<<dim3(TT / 128, HH, BB), 256, ATT_SMEM>>>(
        qhi, qlo, khi, vhi, chi, clo);

    hmma_gemm_kernel<<<dim3(DD / BN, DD / BM, BB), 256, GEMM_SMEM>>>(
        chi, clo, woh, out, nullptr, nullptr, DD, DD,
        (long)DD * TT, (long)TT * DD, 0);
}

// round 9
// speedup vs baseline: 6.0985x; 1.1623x over previous
#include <cuda_runtime.h>
#include <cuda_fp16.h>
#include <math.h>
#include <stdint.h>

#define BB 2
#define TT 2048
#define DD 2048
#define HH 32
#define GG 8
#define HDIM 64
#define GROUPSZ 4
#define KVD (GG*HDIM)   // 512
#define NQKV (DD + 2*KVD)   // 3072

// ---------------------------------------------------------------------------
// Scratch (__device__ globals; no allocations allowed)
// ---------------------------------------------------------------------------
__device__ float g_q[(size_t)BB*TT*HH*HDIM];     // [b][h][t][64] fp32 head-major
__device__ float g_k[(size_t)BB*TT*GG*HDIM];
__device__ float g_v[(size_t)BB*TT*GG*HDIM];

__device__ __half g_xhi[(size_t)BB*TT*DD];
__device__ __half g_xlo[(size_t)BB*TT*DD];
__device__ __half g_qhi[(size_t)BB*TT*HH*HDIM];
__device__ __half g_qlo[(size_t)BB*TT*HH*HDIM];
__device__ __half g_khi[(size_t)BB*TT*GG*HDIM];   // hi only
__device__ __half g_vhi[(size_t)BB*TT*GG*HDIM];   // hi only
__device__ __half g_chi[(size_t)BB*DD*TT];        // ctx^T hi [b][d][t]
__device__ __half g_wqkvhi[(size_t)NQKV*DD];      // hi only
__device__ __half g_wothi[(size_t)DD*DD];         // hi only

// ---------------------------------------------------------------------------
// PTX helpers
// ---------------------------------------------------------------------------
__device__ __forceinline__ uint32_t smem_to_u32(const void* p) {
    uint32_t a;
    asm("{ .reg .u64 tmp; cvta.to.shared.u64 tmp, %1; cvt.u32.u64 %0, tmp; }"
        : "=r"(a) : "l"(p));
    return a;
}
__device__ __forceinline__ void cp_async16(uint32_t dst, const void* src) {
    asm volatile("cp.async.cg.shared.global [%0], [%1], 16;" :: "r"(dst), "l"(src));
}
__device__ __forceinline__ void cp_commit() {
    asm volatile("cp.async.commit_group;" ::: "memory");
}
template <int N> __device__ __forceinline__ void cp_wait() {
    asm volatile("cp.async.wait_group %0;" :: "n"(N) : "memory");
}
__device__ __forceinline__ void ldsm_x4(uint32_t r[4], uint32_t addr) {
    asm volatile("ldmatrix.sync.aligned.m8n8.x4.shared.b16 {%0,%1,%2,%3}, [%4];"
                 : "=r"(r[0]), "=r"(r[1]), "=r"(r[2]), "=r"(r[3]) : "r"(addr));
}
__device__ __forceinline__ void ldsm_x4_t(uint32_t r[4], uint32_t addr) {
    asm volatile("ldmatrix.sync.aligned.m8n8.x4.trans.shared.b16 {%0,%1,%2,%3}, [%4];"
                 : "=r"(r[0]), "=r"(r[1]), "=r"(r[2]), "=r"(r[3]) : "r"(addr));
}
__device__ __forceinline__ void mma_f16(float c[4], const uint32_t a[4],
                                        const uint32_t b0, const uint32_t b1) {
    asm volatile(
        "mma.sync.aligned.m16n8k16.row.col.f32.f16.f16.f32 "
        "{%0,%1,%2,%3}, {%4,%5,%6,%7}, {%8,%9}, {%0,%1,%2,%3};"
        : "+f"(c[0]), "+f"(c[1]), "+f"(c[2]), "+f"(c[3])
        : "r"(a[0]), "r"(a[1]), "r"(a[2]), "r"(a[3]), "r"(b0), "r"(b1));
}
__device__ __forceinline__ uint32_t pkh2(__half a, __half b) {
    __half2 t(a, b);
    return *reinterpret_cast<uint32_t*>(&t);
}

// ---------------------------------------------------------------------------
// fp16 hi/lo split of a float array
// ---------------------------------------------------------------------------
__global__ void split_kernel(const float* __restrict__ in,
                             __half* __restrict__ hi,
                             __half* __restrict__ lo, long n4)
{
    long i = (long)blockIdx.x * blockDim.x + threadIdx.x;
    if (i >= n4) return;
    float4 v = ((const float4*)in)[i];
    __half h0 = __float2half(v.x);
    __half h1 = __float2half(v.y);
    __half h2 = __float2half(v.z);
    __half h3 = __float2half(v.w);
    ((__half2*)hi)[i * 2 + 0] = __half2(h0, h1);
    ((__half2*)hi)[i * 2 + 1] = __half2(h2, h3);
    ((__half2*)lo)[i * 2 + 0] = __half2(__float2half(v.x - __half2float(h0)),
                                        __float2half(v.y - __half2float(h1)));
    ((__half2*)lo)[i * 2 + 1] = __half2(__float2half(v.z - __half2float(h2)),
                                        __float2half(v.w - __half2float(h3)));
}

// ---------------------------------------------------------------------------
// Merged conversion: q -> rope+scale, split hi/lo; k -> rope, hi; v -> hi.
// ---------------------------------------------------------------------------
#define QPAIRS ((long)BB*HH*TT*32)
#define KPAIRS ((long)BB*GG*TT*32)
#define VPAIRS ((long)BB*GG*TT*32)

__global__ void convert_all_kernel(
    const float* __restrict__ qsrc, const float* __restrict__ ksrc,
    const float* __restrict__ vsrc,
    __half* __restrict__ qhi, __half* __restrict__ qlo,
    __half* __restrict__ khi, __half* __restrict__ vhi)
{
    long idx = (long)blockIdx.x * blockDim.x + threadIdx.x;
    const float* src;
    __half *hi, *lo;
    float scale;
    int doRope;
    if (idx < QPAIRS) {
        src = qsrc; hi = qhi; lo = qlo; scale = 0.125f; doRope = 1;
    } else if (idx < QPAIRS + KPAIRS) {
        idx -= QPAIRS;
        src = ksrc; hi = khi; lo = nullptr; scale = 1.0f; doRope = 1;
    } else if (idx < QPAIRS + KPAIRS + VPAIRS) {
        idx -= QPAIRS + KPAIRS;
        src = vsrc; hi = vhi; lo = nullptr; scale = 1.0f; doRope = 0;
    } else return;

    int d = (int)(idx & 31);
    long u = idx >> 5;
    size_t base = (size_t)u * 64 + d;
    float x1 = src[base];
    float x2 = src[base + 32];
    float y1, y2;
    if (doRope) {
        int t = (int)(u & (TT - 1));
        float e = (float)d * (2.0f / (float)HDIM);
        float inv = 1.0f / powf(10000.0f, e);
        float ang = (float)t * inv;
        float s, c;
        sincosf(ang, &s, &c);
        y1 = (x1 * c - x2 * s) * scale;
        y2 = (x2 * c + x1 * s) * scale;
    } else {
        y1 = x1; y2 = x2;
    }
    __half h1 = __float2half(y1);
    __half h2 = __float2half(y2);
    hi[base]      = h1;
    hi[base + 32] = h2;
    if (lo) {
        lo[base]      = __float2half(y1 - __half2float(h1));
        lo[base + 32] = __float2half(y2 - __half2float(h2));
    }
}

// ---------------------------------------------------------------------------
// Transpose: W [K,N] fp32 -> Wt hi [N,K] fp16
// ---------------------------------------------------------------------------
__global__ __launch_bounds__(1024) void transpose_split_kernel(
    const float* __restrict__ W,
    __half* __restrict__ Thi, int K, int N)
{
    __shared__ float tile[32][33];
    int tx = threadIdx.x, ty = threadIdx.y;
    int n0 = blockIdx.x * 32, k0 = blockIdx.y * 32;
    tile[ty][tx] = W[(long)(k0 + ty) * N + n0 + tx];
    __syncthreads();
    Thi[(long)(n0 + ty) * K + k0 + tx] = __float2half(tile[tx][ty]);
}

// ---------------------------------------------------------------------------
// HMMA GEMM: CTA 128x256, warp 64x64, KC=64.
// C = (Ah [+ Al]) * Bh, fp32 accumulate.  Alo==nullptr -> single-term.
// mode 1: fused-QKV head-major scatter epilogue.
// ---------------------------------------------------------------------------
#define BM 128
#define BN 256
#define KC 64
#define OFF_AH 0
#define OFF_AL 16384
#define OFF_BH 32768
#define STAGEB 65536
#define GEMM_SMEM 135168

__global__ __launch_bounds__(256, 1)
void hmma_gemm_kernel(const __half* __restrict__ Ahi,
                      const __half* __restrict__ Alo,
                      const __half* __restrict__ Bhi,
                      float* __restrict__ C, float* __restrict__ Ck,
                      float* __restrict__ Cv, int N, int K,
                      long aBatchStride, long cBatchStride, int mode)
{
    extern __shared__ __align__(128) char smem[];
    const uint32_t smem_base = smem_to_u32(smem);
    const int tid = threadIdx.x;
    const int wid = tid >> 5;
    const int lid = tid & 31;
    const bool two = (Alo != nullptr);

    Ahi += (long)blockIdx.z * aBatchStride;
    if (two) Alo += (long)blockIdx.z * aBatchStride;
    C   += (long)blockIdx.z * cBatchStride;

    const int row0 = blockIdx.y * BM;
    const int col0 = blockIdx.x * BN;
    const int Rw = (wid >> 2) * 64;
    const int Cw = (wid & 3) * 64;

    float acc[4][8][4];
#pragma unroll
    for (int i = 0; i < 4; i++)
#pragma unroll
        for (int j = 0; j < 8; j++)
#pragma unroll
            for (int r = 0; r < 4; r++) acc[i][j][r] = 0.f;

    const int aMat  = lid >> 3;
    const int aRow  = ((aMat & 1) << 3) + (lid & 7);
    const int aCAdd = aMat >> 1;
    const int bRow  = ((lid >> 4) << 3) + (lid & 7);
    const int bCAdd = (lid >> 3) & 1;

    const int nch = K / KC;

    auto load_stage = [&](int buf, int k0) {
        uint32_t stage = smem_base + buf * STAGEB;
#pragma unroll
        for (int i = 0; i < 4; i++) {
            int e = i * 256 + tid;
            int r = e >> 3, c = e & 7;
            uint32_t swoff = r * 128 + ((c ^ (r & 7)) << 4);
            const size_t gsrc = (size_t)(row0 + r) * K + k0 + c * 8;
            cp_async16(stage + OFF_AH + swoff, Ahi + gsrc);
            if (two) cp_async16(stage + OFF_AL + swoff, Alo + gsrc);
        }
#pragma unroll
        for (int i = 0; i < 8; i++) {
            int e = i * 256 + tid;
            int r = e >> 3, c = e & 7;
            uint32_t swoff = r * 128 + ((c ^ (r & 7)) << 4);
            cp_async16(stage + OFF_BH + swoff, Bhi + (size_t)(col0 + r) * K + k0 + c * 8);
        }
        cp_commit();
    };

    load_stage(0, 0);

    for (int ch = 0; ch < nch; ch++) {
        if (ch + 1 < nch) {
            load_stage((ch + 1) & 1, (ch + 1) * KC);
            cp_wait<1>();
        } else {
            cp_wait<0>();
        }
        __syncthreads();

        uint32_t stage = smem_base + (ch & 1) * STAGEB;

#pragma unroll
        for (int ks = 0; ks < 4; ks++) {
            const int c16 = ks * 2;
            uint32_t ah[4][4], al[4][4];
#pragma unroll
            for (int mf = 0; mf < 4; mf++) {
                int r = Rw + mf * 16 + aRow;
                uint32_t off = r * 128 + (((c16 + aCAdd) ^ (r & 7)) << 4);
                ldsm_x4(ah[mf], stage + OFF_AH + off);
                if (two) ldsm_x4(al[mf], stage + OFF_AL + off);
            }
#pragma unroll
            for (int np = 0; np < 4; np++) {
                int r = Cw + np * 16 + bRow;
                uint32_t off = r * 128 + (((c16 + bCAdd) ^ (r & 7)) << 4);
                uint32_t bh4[4];
                ldsm_x4(bh4, stage + OFF_BH + off);
                const int nf0 = np * 2;
#pragma unroll
                for (int mf = 0; mf < 4; mf++) {
                    mma_f16(acc[mf][nf0],     ah[mf], bh4[0], bh4[1]);
                    mma_f16(acc[mf][nf0 + 1], ah[mf], bh4[2], bh4[3]);
                }
                if (two) {
#pragma unroll
                    for (int mf = 0; mf < 4; mf++) {
                        mma_f16(acc[mf][nf0],     al[mf], bh4[0], bh4[1]);
                        mma_f16(acc[mf][nf0 + 1], al[mf], bh4[2], bh4[3]);
                    }
                }
            }
        }
        __syncthreads();
    }

    // epilogue: stage fp32 through smem (pitch 260), coalesced stores
    float* stage = (float*)smem;
    const int g  = lid >> 2;
    const int tg = lid & 3;
#pragma unroll
    for (int mf = 0; mf < 4; mf++)
#pragma unroll
        for (int nf = 0; nf < 8; nf++) {
            int row = Rw + mf * 16 + g;
            int col = Cw + nf * 8 + 2 * tg;
            stage[row * 260 + col]           = acc[mf][nf][0];
            stage[row * 260 + col + 1]       = acc[mf][nf][1];
            stage[(row + 8) * 260 + col]     = acc[mf][nf][2];
            stage[(row + 8) * 260 + col + 1] = acc[mf][nf][3];
        }
    __syncthreads();
#pragma unroll
    for (int i = 0; i < 32; i++) {
        int e = i * 256 + tid;
        int r = e >> 6;
        int c4 = e & 63;
        float4 v = *(float4*)&stage[r * 260 + c4 * 4];
        if (mode == 1) {
            int m = row0 + r;
            int bb = m >> 11;
            int t = m & (TT - 1);
            int col = col0 + c4 * 4;
            float* dstBase;
            int head, nh;
            if (col < DD)            { dstBase = C;  head = col >> 6; nh = HH; }
            else if (col < DD + KVD) { dstBase = Ck; head = (col - DD) >> 6; nh = GG; }
            else                     { dstBase = Cv; head = (col - DD - KVD) >> 6; nh = GG; }
            size_t dst = (((size_t)bb * nh + head) * TT + t) * 64 + (col & 63);
            *(float4*)&dstBase[dst] = v;
        } else {
            *(float4*)&C[(size_t)(row0 + r) * N + col0 + c4 * 4] = v;
        }
    }
}

// ---------------------------------------------------------------------------
// HMMA flash attention (causal, GQA), fp16.
// S = (Qh+Ql) Kh (2 passes); P hi-only; O += Ph Vh (1 pass).
// Writes ctx^T hi fp16 only.
// ---------------------------------------------------------------------------
#define ATT_SMEM 65536   // Q 32K | kv buf0 16K | kv buf1 16K

__global__ __launch_bounds__(256, 1) void attn_hmma_kernel(
    const __half* __restrict__ qhi, const __half* __restrict__ qlo,
    const __half* __restrict__ khi, const __half* __restrict__ vhi,
    __half* __restrict__ chi)
{
    extern __shared__ __align__(128) char smem[];
    const uint32_t sb = smem_to_u32(smem);
    const int tid = threadIdx.x, wid = tid >> 5, lid = tid & 31;
    const int qt = gridDim.x - 1 - blockIdx.x;
    const int h = blockIdx.y, b = blockIdx.z;
    const int g = h / GROUPSZ;
    const int tg = lid & 3, gr = lid >> 2;

    const size_t qoff   = ((size_t)(b * HH + h) * TT + (size_t)qt * 128) * 64;
    const size_t kvoff0 = ((size_t)(b * GG + g) * TT) * 64;

    auto kv_load = [&](int buf, int kt) {
        const __half* srcs[2] = {
            khi + kvoff0 + (size_t)kt * 64 * 64,
            vhi + kvoff0 + (size_t)kt * 64 * 64 };
        uint32_t bbase = sb + 32768 + buf * 16384;
#pragma unroll
        for (int i = 0; i < 4; i++) {
            int e = i * 256 + tid;
            int part = e >> 9, rr = (e >> 3) & 63, c = e & 7;
            cp_async16(bbase + part * 8192 + rr * 128 + ((c ^ (rr & 7)) << 4),
                       srcs[part] + (size_t)rr * 64 + c * 8);
        }
        cp_commit();
    };

#pragma unroll
    for (int i = 0; i < 8; i++) {
        int e = i * 256 + tid;
        int part = e >> 10, rr = (e >> 3) & 127, c = e & 7;
        const __half* s = (part ? qlo : qhi) + qoff;
        cp_async16(sb + part * 16384 + rr * 128 + ((c ^ (rr & 7)) << 4),
                   s + (size_t)rr * 64 + c * 8);
    }
    kv_load(1, 0);
    cp_wait<0>();
    __syncthreads();

    uint32_t qhf[4][4], qlf[4][4];
    {
        const int aMat = lid >> 3;
        const int aRow = ((aMat & 1) << 3) + (lid & 7);
        const int aCAdd = aMat >> 1;
#pragma unroll
        for (int kf = 0; kf < 4; kf++) {
            int r = wid * 16 + aRow;
            uint32_t off = r * 128 + (((2 * kf + aCAdd) ^ (r & 7)) << 4);
            ldsm_x4(qhf[kf], sb + off);
            ldsm_x4(qlf[kf], sb + 16384 + off);
        }
    }
    __syncthreads();

    float O[8][4];
#pragma unroll
    for (int nf = 0; nf < 8; nf++)
#pragma unroll
        for (int r = 0; r < 4; r++) O[nf][r] = 0.f;
    float m0 = -INFINITY, m1 = -INFINITY, l0 = 0.f, l1 = 0.f;

    const int nkt = 2 * qt + 2;
    const int bRow = ((lid >> 4) << 3) + (lid & 7);
    const int bCAdd = (lid >> 3) & 1;

    for (int kt = 0; kt < nkt; kt++) {
        if (kt + 1 < nkt) { kv_load(kt & 1, kt + 1); cp_wait<1>(); }
        else              { cp_wait<0>(); }
        __syncthreads();
        const uint32_t kv = sb + 32768 + ((kt + 1) & 1) * 16384;

        float S[8][4];
#pragma unroll
        for (int nf = 0; nf < 8; nf++)
#pragma unroll
            for (int r = 0; r < 4; r++) S[nf][r] = 0.f;

#pragma unroll
        for (int ks = 0; ks < 4; ks++) {
            uint32_t khf[4][4];
#pragma unroll
            for (int np = 0; np < 4; np++) {
                int r = np * 16 + bRow;
                uint32_t off = r * 128 + (((2 * ks + bCAdd) ^ (r & 7)) << 4);
                ldsm_x4(khf[np], kv + off);
            }
#pragma unroll
            for (int np = 0; np < 4; np++) {
                mma_f16(S[np * 2],     qhf[ks], khf[np][0], khf[np][1]);
                mma_f16(S[np * 2 + 1], qhf[ks], khf[np][2], khf[np][3]);
            }
#pragma unroll
            for (int np = 0; np < 4; np++) {
                mma_f16(S[np * 2],     qlf[ks], khf[np][0], khf[np][1]);
                mma_f16(S[np * 2 + 1], qlf[ks], khf[np][2], khf[np][3]);
            }
        }

        const int row0 = qt * 128 + wid * 16 + gr;
        if (kt * 64 + 63 > row0) {
#pragma unroll
            for (int nf = 0; nf < 8; nf++) {
                int colb = kt * 64 + 8 * nf + 2 * tg;
                if (colb     > row0)     S[nf][0] = -INFINITY;
                if (colb + 1 > row0)     S[nf][1] = -INFINITY;
                if (colb     > row0 + 8) S[nf][2] = -INFINITY;
                if (colb + 1 > row0 + 8) S[nf][3] = -INFINITY;
            }
        }

        float mt0 = m0, mt1 = m1;
#pragma unroll
        for (int nf = 0; nf < 8; nf++) {
            mt0 = fmaxf(mt0, fmaxf(S[nf][0], S[nf][1]));
            mt1 = fmaxf(mt1, fmaxf(S[nf][2], S[nf][3]));
        }
        mt0 = fmaxf(mt0, __shfl_xor_sync(0xffffffffu, mt0, 1));
        mt0 = fmaxf(mt0, __shfl_xor_sync(0xffffffffu, mt0, 2));
        mt1 = fmaxf(mt1, __shfl_xor_sync(0xffffffffu, mt1, 1));
        mt1 = fmaxf(mt1, __shfl_xor_sync(0xffffffffu, mt1, 2));
        float c0 = __expf(m0 - mt0), c1 = __expf(m1 - mt1);
        m0 = mt0; m1 = mt1;
        float ls0 = 0.f, ls1 = 0.f;
#pragma unroll
        for (int nf = 0; nf < 8; nf++) {
            S[nf][0] = __expf(S[nf][0] - mt0); ls0 += S[nf][0];
            S[nf][1] = __expf(S[nf][1] - mt0); ls0 += S[nf][1];
            S[nf][2] = __expf(S[nf][2] - mt1); ls1 += S[nf][2];
            S[nf][3] = __expf(S[nf][3] - mt1); ls1 += S[nf][3];
        }
        l0 = l0 * c0 + ls0;
        l1 = l1 * c1 + ls1;
#pragma unroll
        for (int nf = 0; nf < 8; nf++) {
            O[nf][0] *= c0; O[nf][1] *= c0; O[nf][2] *= c1; O[nf][3] *= c1;
        }

        // O += P V  (P hi-only)
#pragma unroll
        for (int ks = 0; ks < 4; ks++) {
            uint32_t pah[4];
            pah[0] = pkh2(__float2half(S[2*ks][0]),   __float2half(S[2*ks][1]));
            pah[1] = pkh2(__float2half(S[2*ks][2]),   __float2half(S[2*ks][3]));
            pah[2] = pkh2(__float2half(S[2*ks+1][0]), __float2half(S[2*ks+1][1]));
            pah[3] = pkh2(__float2half(S[2*ks+1][2]), __float2half(S[2*ks+1][3]));
            uint32_t vhf[4][4];
            {
                int blk = lid >> 3;
                int r = ks * 16 + ((blk & 1) << 3) + (lid & 7);
#pragma unroll
                for (int np = 0; np < 4; np++) {
                    int chunk = 2 * np + (blk >> 1);
                    uint32_t off = r * 128 + ((chunk ^ (r & 7)) << 4);
                    ldsm_x4_t(vhf[np], kv + 8192 + off);
                }
            }
#pragma unroll
            for (int np = 0; np < 4; np++) {
                mma_f16(O[np * 2],     pah, vhf[np][0], vhf[np][1]);
                mma_f16(O[np * 2 + 1], pah, vhf[np][2], vhf[np][3]);
            }
        }
        __syncthreads();
    }

    l0 += __shfl_xor_sync(0xffffffffu, l0, 1);
    l0 += __shfl_xor_sync(0xffffffffu, l0, 2);
    l1 += __shfl_xor_sync(0xffffffffu, l1, 1);
    l1 += __shfl_xor_sync(0xffffffffu, l1, 2);
    const float i0 = 1.f / l0, i1 = 1.f / l1;

    float* stg = (float*)smem;
#pragma unroll
    for (int nf = 0; nf < 8; nf++) {
        int c = 8 * nf + 2 * tg;
        int q0 = wid * 16 + gr;
        stg[c * 132 + q0]           = O[nf][0] * i0;
        stg[(c + 1) * 132 + q0]     = O[nf][1] * i0;
        stg[c * 132 + q0 + 8]       = O[nf][2] * i1;
        stg[(c + 1) * 132 + q0 + 8] = O[nf][3] * i1;
    }
    __syncthreads();

    const size_t ob = ((size_t)b * DD + (size_t)h * 64) * TT + (size_t)qt * 128;
#pragma unroll
    for (int i = 0; i < 8; i++) {
        int e = i * 256 + tid;
        int c = e >> 5;
        int q4 = e & 31;
        float4 v = *(float4*)&stg[c * 132 + q4 * 4];
        uint2 hv;
        hv.x = pkh2(__float2half(v.x), __float2half(v.y));
        hv.y = pkh2(__float2half(v.z), __float2half(v.w));
        *(uint2*)&chi[ob + (size_t)c * TT + q4 * 4] = hv;
    }
}

// ---------------------------------------------------------------------------
// Launch
// ---------------------------------------------------------------------------
extern "C" void kernel_launch(void* const* d_in, const int* in_sizes, int n_in,
                              void* d_out, int out_size)
{
    const float* x  = (const float*)d_in[0];
    const float* Wq = (const float*)d_in[1];
    const float* Wk = (const float*)d_in[2];
    const float* Wv = (const float*)d_in[3];
    const float* Wo = (const float*)d_in[4];
    float* out = (float*)d_out;

    float *qb, *kb, *vb;
    cudaGetSymbolAddress((void**)&qb, g_q);
    cudaGetSymbolAddress((void**)&kb, g_k);
    cudaGetSymbolAddress((void**)&vb, g_v);
    __half *xhi, *xlo, *chi, *qhi, *qlo, *khi, *vhi, *wqkvh, *woh;
    cudaGetSymbolAddress((void**)&xhi, g_xhi);
    cudaGetSymbolAddress((void**)&xlo, g_xlo);
    cudaGetSymbolAddress((void**)&chi, g_chi);
    cudaGetSymbolAddress((void**)&qhi, g_qhi);
    cudaGetSymbolAddress((void**)&qlo, g_qlo);
    cudaGetSymbolAddress((void**)&khi, g_khi);
    cudaGetSymbolAddress((void**)&vhi, g_vhi);
    cudaGetSymbolAddress((void**)&wqkvh, g_wqkvhi);
    cudaGetSymbolAddress((void**)&woh, g_wothi);

    const int M = BB * TT;   // 4096

    {
        long n4 = (long)M * DD / 4;
        split_kernel<<<(int)((n4 + 255) / 256), 256>>>(x, xhi, xlo, n4);
    }
    {
        dim3 blk(32, 32);
        transpose_split_kernel<<<dim3(DD / 32,  DD / 32), blk>>>(Wq, wqkvh, DD, DD);
        transpose_split_kernel<<<dim3(KVD / 32, DD / 32), blk>>>(
            Wk, wqkvh + (size_t)DD * DD, DD, KVD);
        transpose_split_kernel<<<dim3(KVD / 32, DD / 32), blk>>>(
            Wv, wqkvh + (size_t)(DD + KVD) * DD, DD, KVD);
        transpose_split_kernel<<<dim3(DD / 32,  DD / 32), blk>>>(Wo, woh, DD, DD);
    }

    // fused QKV projection (2-term A)
    cudaFuncSetAttribute(hmma_gemm_kernel, cudaFuncAttributeMaxDynamicSharedMemorySize,
                         GEMM_SMEM);
    hmma_gemm_kernel<<<dim3(NQKV / BN, M / BM, 1), 256, GEMM_SMEM>>>(
        xhi, xlo, wqkvh, qb, kb, vb, NQKV, DD, 0, 0, 1);

    {
        long total = QPAIRS + KPAIRS + VPAIRS;
        convert_all_kernel<<<(int)((total + 255) / 256), 256>>>(
            qb, kb, vb, qhi, qlo, khi, vhi);
    }

    cudaFuncSetAttribute(attn_hmma_kernel, cudaFuncAttributeMaxDynamicSharedMemorySize,
                         ATT_SMEM);
    attn_hmma_kernel<<<dim3(TT / 128, HH, BB), 256, ATT_SMEM>>>(
        qhi, qlo, khi, vhi, chi);

    // final projection (single-term A: ctx hi only)
    hmma_gemm_kernel<<<dim3(DD / BN, DD / BM, BB), 256, GEMM_SMEM>>>(
        chi, nullptr, woh, out, nullptr, nullptr, DD, DD,
        (long)DD * TT, (long)TT * DD, 0);
}